// round 1
// baseline (speedup 1.0000x reference)
#include <cuda_runtime.h>
#include <cuda_bf16.h>
#include <math.h>

// Problem constants
#define Bn   2
#define Ln   2048
#define Hn   16
#define KVn  4
#define Dn   128
#define HIDn 2048

// Scratch (static device globals; no runtime allocation)
__device__ float g_q [(size_t)Bn * Hn  * Ln * Dn];  // [b][h][l][d]
__device__ float g_k [(size_t)Bn * KVn * Ln * Dn];  // [b][g][l][d]
__device__ float g_v [(size_t)Bn * KVn * Ln * Dn];  // [b][g][l][d]
__device__ float g_ao[(size_t)Bn * Ln * Hn * Dn];   // [b][l][h][d]

// ---------------------------------------------------------------------------
// Generic tiled SGEMM: C[M=4096, N] = A[4096, 2048] @ W[2048, N]
// MODE 0: out -> g_q  (heads=16, transposed [b][h][l][d])
// MODE 1: out -> g_k  (heads=4)
// MODE 2: out -> g_v  (heads=4)
// MODE 3: A = g_ao, out -> plain row-major param
// BM=BN=128, BK=16, 256 threads, 8x8 per thread, double-buffered smem.
// ---------------------------------------------------------------------------
template <int MODE>
__global__ __launch_bounds__(256, 2)
void sgemm_kernel(const float* __restrict__ Ap, const float* __restrict__ W,
                  float* __restrict__ outp, int N)
{
    const float* A = (MODE == 3) ? (const float*)g_ao : Ap;

    __shared__ float As[2][16][128];  // [buf][k][m]
    __shared__ float Bs[2][16][128];  // [buf][k][n]

    const int tid = threadIdx.x;
    const int m0 = blockIdx.y * 128;
    const int n0 = blockIdx.x * 128;
    const int ty = tid >> 4;   // 0..15 -> rows ty*8..
    const int tx = tid & 15;   // 0..15 -> cols tx*8..

    const int arw = tid >> 2;          // 0..63
    const int ac  = (tid & 3) * 4;     // 0,4,8,12
    const int brw = tid >> 5;          // 0..7
    const int bc  = (tid & 31) * 4;    // 0..124

    float4 ra0, ra1, rb0, rb1;

#define SG_FETCH(kt)                                                                  \
    do {                                                                              \
        ra0 = *(const float4*)&A[(size_t)(m0 + arw) * HIDn + (kt) * 16 + ac];         \
        ra1 = *(const float4*)&A[(size_t)(m0 + 64 + arw) * HIDn + (kt) * 16 + ac];    \
        rb0 = *(const float4*)&W[(size_t)((kt) * 16 + brw) * N + n0 + bc];            \
        rb1 = *(const float4*)&W[(size_t)((kt) * 16 + 8 + brw) * N + n0 + bc];        \
    } while (0)

#define SG_STASH(buf)                                                                 \
    do {                                                                              \
        As[buf][ac + 0][arw] = ra0.x; As[buf][ac + 1][arw] = ra0.y;                   \
        As[buf][ac + 2][arw] = ra0.z; As[buf][ac + 3][arw] = ra0.w;                   \
        As[buf][ac + 0][arw + 64] = ra1.x; As[buf][ac + 1][arw + 64] = ra1.y;         \
        As[buf][ac + 2][arw + 64] = ra1.z; As[buf][ac + 3][arw + 64] = ra1.w;         \
        *(float4*)&Bs[buf][brw][bc]     = rb0;                                        \
        *(float4*)&Bs[buf][brw + 8][bc] = rb1;                                        \
    } while (0)

    float acc[8][8];
#pragma unroll
    for (int i = 0; i < 8; i++)
#pragma unroll
        for (int j = 0; j < 8; j++) acc[i][j] = 0.0f;

    const int NT = HIDn / 16;  // 128
    SG_FETCH(0);
    SG_STASH(0);
    __syncthreads();

    for (int kt = 0; kt < NT; kt++) {
        const int cur = kt & 1;
        if (kt + 1 < NT) SG_FETCH(kt + 1);

#pragma unroll
        for (int kk = 0; kk < 16; kk++) {
            float4 a0 = *(float4*)&As[cur][kk][ty * 8];
            float4 a1 = *(float4*)&As[cur][kk][ty * 8 + 4];
            float4 b0 = *(float4*)&Bs[cur][kk][tx * 8];
            float4 b1 = *(float4*)&Bs[cur][kk][tx * 8 + 4];
            float av[8] = {a0.x, a0.y, a0.z, a0.w, a1.x, a1.y, a1.z, a1.w};
            float bv[8] = {b0.x, b0.y, b0.z, b0.w, b1.x, b1.y, b1.z, b1.w};
#pragma unroll
            for (int i = 0; i < 8; i++)
#pragma unroll
                for (int j = 0; j < 8; j++) acc[i][j] += av[i] * bv[j];
        }

        if (kt + 1 < NT) SG_STASH(cur ^ 1);
        __syncthreads();
    }

    // Epilogue
    if (MODE == 3) {
#pragma unroll
        for (int i = 0; i < 8; i++) {
            int row = m0 + ty * 8 + i;
            float4 v0 = {acc[i][0], acc[i][1], acc[i][2], acc[i][3]};
            float4 v1 = {acc[i][4], acc[i][5], acc[i][6], acc[i][7]};
            float* op = outp + (size_t)row * N + n0 + tx * 8;
            *(float4*)op = v0;
            *(float4*)(op + 4) = v1;
        }
    } else {
        float* out = (MODE == 0) ? g_q : (MODE == 1 ? g_k : g_v);
        const int NH = (MODE == 0) ? Hn : KVn;
        const int h = n0 >> 7;  // BN==Dn==128, so each block covers one head
#pragma unroll
        for (int i = 0; i < 8; i++) {
            int m = m0 + ty * 8 + i;
            int b = m >> 11;          // L = 2048
            int l = m & (Ln - 1);
            float4 v0 = {acc[i][0], acc[i][1], acc[i][2], acc[i][3]};
            float4 v1 = {acc[i][4], acc[i][5], acc[i][6], acc[i][7]};
            float* op = out + (((size_t)b * NH + h) * Ln + l) * Dn + tx * 8;
            *(float4*)op = v0;
            *(float4*)(op + 4) = v1;
        }
    }
#undef SG_FETCH
#undef SG_STASH
}

// ---------------------------------------------------------------------------
// RMSNorm + RoPE applied in-place to g_q (16 heads) and g_k (4 heads).
// One warp per (b, l, head) vector of 128 floats.
// ---------------------------------------------------------------------------
__global__ __launch_bounds__(256)
void norm_rope_kernel(const float* __restrict__ cosb, const float* __restrict__ sinb,
                      const float* __restrict__ qw, const float* __restrict__ kw)
{
    const int gw   = (blockIdx.x * 256 + threadIdx.x) >> 5;
    const int lane = threadIdx.x & 31;
    const int slot = gw % (Hn + KVn);
    const int bl   = gw / (Hn + KVn);
    const int l    = bl & (Ln - 1);
    const int b    = bl >> 11;

    float* ptr;
    const float* nw;
    if (slot < Hn) {
        ptr = g_q + (((size_t)b * Hn + slot) * Ln + l) * Dn;
        nw = qw;
    } else {
        ptr = g_k + (((size_t)b * KVn + (slot - Hn)) * Ln + l) * Dn;
        nw = kw;
    }

    float x0 = ptr[lane], x1 = ptr[lane + 32], x2 = ptr[lane + 64], x3 = ptr[lane + 96];
    float ss = x0 * x0 + x1 * x1 + x2 * x2 + x3 * x3;
#pragma unroll
    for (int o = 16; o; o >>= 1) ss += __shfl_xor_sync(0xffffffffu, ss, o);
    const float r = rsqrtf(ss * (1.0f / Dn) + 1e-6f);
    x0 *= r * nw[lane];
    x1 *= r * nw[lane + 32];
    x2 *= r * nw[lane + 64];
    x3 *= r * nw[lane + 96];

    const float* cp = cosb + ((size_t)b * Ln + l) * Dn;
    const float* sp = sinb + ((size_t)b * Ln + l) * Dn;
    float c0 = cp[lane], c1 = cp[lane + 32], c2 = cp[lane + 64], c3 = cp[lane + 96];
    float s0 = sp[lane], s1 = sp[lane + 32], s2 = sp[lane + 64], s3 = sp[lane + 96];

    // rotate_half: d<64 -> -x[d+64], d>=64 -> x[d-64]
    ptr[lane]      = x0 * c0 - x2 * s0;
    ptr[lane + 32] = x1 * c1 - x3 * s1;
    ptr[lane + 64] = x2 * c2 + x0 * s2;
    ptr[lane + 96] = x3 * c3 + x1 * s3;
}

// ---------------------------------------------------------------------------
// Flash attention, fp32. Block = (query tile of 64) x (head) x (batch).
// 256 threads: thread (ty,tx) owns 4 query rows x 8 cols. Key tiles of 128.
// Online softmax; result -> g_ao[b][l][h][d].
// ---------------------------------------------------------------------------
#define QS_STR 68
#define KS_STR 132
#define ATTN_SMEM_FLOATS (128 * QS_STR + 128 * KS_STR + 128 * 128 + 128 * QS_STR)

__global__ __launch_bounds__(256, 1)
void attn_kernel()
{
    extern __shared__ float sm[];
    float* Qs = sm;                                  // [d][row]  128 x 68
    float* Ks = Qs + 128 * QS_STR;                   // [d][col]  128 x 132
    float* Vs = Ks + 128 * KS_STR;                   // [col][d]  128 x 128
    float* Ps = Vs + 128 * 128;                      // [col][row] 128 x 68

    const int qt = blockIdx.x;        // 0..31
    const int h  = blockIdx.y;        // 0..15
    const int b  = blockIdx.z;        // 0..1
    const int g  = h >> 2;            // n_rep = 4

    const int tid = threadIdx.x;
    const int ty = tid >> 4;          // 0..15, rows ty*4..
    const int tx = tid & 15;          // 0..15, cols tx*8..

    const float* Qg = g_q + (((size_t)b * Hn + h) * Ln + qt * 64) * Dn;
    const float* Kg = g_k + ((size_t)b * KVn + g) * Ln * Dn;
    const float* Vg = g_v + ((size_t)b * KVn + g) * Ln * Dn;

    const float SCALE = 0.08838834764831845f;  // 128^-0.5

    // Load Q (64 x 128) transposed
#pragma unroll
    for (int it = 0; it < 8; it++) {
        int f = tid + it * 256;
        int row = f >> 5, d4 = (f & 31) * 4;
        float4 v = *(const float4*)&Qg[row * Dn + d4];
        Qs[(d4 + 0) * QS_STR + row] = v.x;
        Qs[(d4 + 1) * QS_STR + row] = v.y;
        Qs[(d4 + 2) * QS_STR + row] = v.z;
        Qs[(d4 + 3) * QS_STR + row] = v.w;
    }

    float o[4][8];
#pragma unroll
    for (int i = 0; i < 4; i++)
#pragma unroll
        for (int j = 0; j < 8; j++) o[i][j] = 0.0f;
    float mrow[4] = {-INFINITY, -INFINITY, -INFINITY, -INFINITY};
    float lrow[4] = {0.0f, 0.0f, 0.0f, 0.0f};

    for (int kt = 0; kt < Ln / 128; kt++) {
        __syncthreads();  // prev PV done (Ps/Vs free), Ks free
        // Load K,V tile (128 keys x 128 dims)
#pragma unroll
        for (int it = 0; it < 16; it++) {
            int f = tid + it * 256;
            int row = f >> 5, d4 = (f & 31) * 4;
            float4 kv = *(const float4*)&Kg[(size_t)(kt * 128 + row) * Dn + d4];
            Ks[(d4 + 0) * KS_STR + row] = kv.x;
            Ks[(d4 + 1) * KS_STR + row] = kv.y;
            Ks[(d4 + 2) * KS_STR + row] = kv.z;
            Ks[(d4 + 3) * KS_STR + row] = kv.w;
            float4 vv = *(const float4*)&Vg[(size_t)(kt * 128 + row) * Dn + d4];
            *(float4*)&Vs[row * 128 + d4] = vv;
        }
        __syncthreads();

        // S = Q @ K^T  (per-thread 4x8)
        float s[4][8];
#pragma unroll
        for (int i = 0; i < 4; i++)
#pragma unroll
            for (int j = 0; j < 8; j++) s[i][j] = 0.0f;

        for (int d = 0; d < 128; d++) {
            float4 a  = *(float4*)&Qs[d * QS_STR + ty * 4];
            float4 b0 = *(float4*)&Ks[d * KS_STR + tx * 8];
            float4 b1 = *(float4*)&Ks[d * KS_STR + tx * 8 + 4];
            float av[4] = {a.x, a.y, a.z, a.w};
            float bv[8] = {b0.x, b0.y, b0.z, b0.w, b1.x, b1.y, b1.z, b1.w};
#pragma unroll
            for (int i = 0; i < 4; i++)
#pragma unroll
                for (int j = 0; j < 8; j++) s[i][j] += av[i] * bv[j];
        }

        // Online softmax
#pragma unroll
        for (int i = 0; i < 4; i++) {
#pragma unroll
            for (int j = 0; j < 8; j++) s[i][j] *= SCALE;
            float rm = s[i][0];
#pragma unroll
            for (int j = 1; j < 8; j++) rm = fmaxf(rm, s[i][j]);
#pragma unroll
            for (int off = 8; off; off >>= 1)
                rm = fmaxf(rm, __shfl_xor_sync(0xffffffffu, rm, off));
            float mnew = fmaxf(mrow[i], rm);
            float corr = __expf(mrow[i] - mnew);
            mrow[i] = mnew;
            float rsum = 0.0f;
#pragma unroll
            for (int j = 0; j < 8; j++) {
                s[i][j] = __expf(s[i][j] - mnew);
                rsum += s[i][j];
            }
#pragma unroll
            for (int off = 8; off; off >>= 1)
                rsum += __shfl_xor_sync(0xffffffffu, rsum, off);
            lrow[i] = lrow[i] * corr + rsum;
#pragma unroll
            for (int j = 0; j < 8; j++) o[i][j] *= corr;
        }

        // Write P transposed: Ps[col][row]
#pragma unroll
        for (int i = 0; i < 4; i++)
#pragma unroll
            for (int j = 0; j < 8; j++)
                Ps[(tx * 8 + j) * QS_STR + (ty * 4 + i)] = s[i][j];
        __syncthreads();

        // O += P @ V
        for (int c = 0; c < 128; c++) {
            float4 a  = *(float4*)&Ps[c * QS_STR + ty * 4];
            float4 b0 = *(float4*)&Vs[c * 128 + tx * 8];
            float4 b1 = *(float4*)&Vs[c * 128 + tx * 8 + 4];
            float av[4] = {a.x, a.y, a.z, a.w};
            float bv[8] = {b0.x, b0.y, b0.z, b0.w, b1.x, b1.y, b1.z, b1.w};
#pragma unroll
            for (int i = 0; i < 4; i++)
#pragma unroll
                for (int j = 0; j < 8; j++) o[i][j] += av[i] * bv[j];
        }
    }

    // Epilogue: normalize and write to [b][l][h][d]
#pragma unroll
    for (int i = 0; i < 4; i++) {
        float inv = 1.0f / lrow[i];
        int l = qt * 64 + ty * 4 + i;
        float* op = g_ao + (((size_t)b * Ln + l) * Hn + h) * Dn + tx * 8;
        float4 v0 = {o[i][0] * inv, o[i][1] * inv, o[i][2] * inv, o[i][3] * inv};
        float4 v1 = {o[i][4] * inv, o[i][5] * inv, o[i][6] * inv, o[i][7] * inv};
        *(float4*)op = v0;
        *(float4*)(op + 4) = v1;
    }
}

// ---------------------------------------------------------------------------
extern "C" void kernel_launch(void* const* d_in, const int* in_sizes, int n_in,
                              void* d_out, int out_size)
{
    const float* hs = (const float*)d_in[0];
    const float* cs = (const float*)d_in[1];
    const float* sn = (const float*)d_in[2];
    const float* Wq = (const float*)d_in[3];
    const float* Wk = (const float*)d_in[4];
    const float* Wv = (const float*)d_in[5];
    const float* Wo = (const float*)d_in[6];
    const float* qw = (const float*)d_in[7];
    const float* kw = (const float*)d_in[8];
    float* out = (float*)d_out;

    // QKV projections (write transposed head-major scratch)
    sgemm_kernel<0><<<dim3(HIDn / 128, (Bn * Ln) / 128), 256>>>(hs, Wq, nullptr, Hn * Dn);
    sgemm_kernel<1><<<dim3((KVn * Dn) / 128, (Bn * Ln) / 128), 256>>>(hs, Wk, nullptr, KVn * Dn);
    sgemm_kernel<2><<<dim3((KVn * Dn) / 128, (Bn * Ln) / 128), 256>>>(hs, Wv, nullptr, KVn * Dn);

    // RMSNorm + RoPE (in-place on g_q, g_k)
    {
        int warps = Bn * Ln * (Hn + KVn);   // 81920
        norm_rope_kernel<<<warps / 8, 256>>>(cs, sn, qw, kw);
    }

    // Flash attention
    {
        int smem_bytes = ATTN_SMEM_FLOATS * (int)sizeof(float);  // 202752
        cudaFuncSetAttribute(attn_kernel, cudaFuncAttributeMaxDynamicSharedMemorySize,
                             smem_bytes);
        attn_kernel<<<dim3(Ln / 64, Hn, Bn), 256, smem_bytes>>>();
    }

    // Output projection
    sgemm_kernel<3><<<dim3(HIDn / 128, (Bn * Ln) / 128), 256>>>(nullptr, Wo, out, HIDn);
}

// round 5
// speedup vs baseline: 1.3486x; 1.3486x over previous
#include <cuda_runtime.h>
#include <cuda_bf16.h>
#include <math.h>
#include <stdint.h>

// Problem constants
#define Bn   2
#define Ln   2048
#define Hn   16
#define KVn  4
#define Dn   128
#define HIDn 2048

// ---------------------------------------------------------------------------
// Portable tensor-core helpers (sm_80+ PTX only; no tcgen05 — harness ptxas
// targets sm_103 without the 'a' feature set)
// ---------------------------------------------------------------------------
__device__ __forceinline__ uint32_t smem_to_u32(const void* p) {
    uint32_t a;
    asm("{ .reg .u64 t; cvta.to.shared.u64 t, %1; cvt.u32.u64 %0, t; }" : "=r"(a) : "l"(p));
    return a;
}
__device__ __forceinline__ void ldm_x4(uint32_t* r, uint32_t a) {
    asm volatile("ldmatrix.sync.aligned.m8n8.x4.shared.b16 {%0,%1,%2,%3}, [%4];"
        : "=r"(r[0]), "=r"(r[1]), "=r"(r[2]), "=r"(r[3]) : "r"(a));
}
__device__ __forceinline__ void ldm_x2(uint32_t* r, uint32_t a) {
    asm volatile("ldmatrix.sync.aligned.m8n8.x2.shared.b16 {%0,%1}, [%2];"
        : "=r"(r[0]), "=r"(r[1]) : "r"(a));
}
__device__ __forceinline__ void mma16816(float* c, const uint32_t* a, const uint32_t* b) {
    asm volatile("mma.sync.aligned.m16n8k16.row.col.f32.bf16.bf16.f32 "
        "{%0,%1,%2,%3}, {%4,%5,%6,%7}, {%8,%9}, {%0,%1,%2,%3};"
        : "+f"(c[0]), "+f"(c[1]), "+f"(c[2]), "+f"(c[3])
        : "r"(a[0]), "r"(a[1]), "r"(a[2]), "r"(a[3]), "r"(b[0]), "r"(b[1]));
}
__device__ __forceinline__ void cpasync16(uint32_t s, const void* g) {
    asm volatile("cp.async.cg.shared.global [%0], [%1], 16;" :: "r"(s), "l"(g));
}
#define CP_COMMIT() asm volatile("cp.async.commit_group;" ::: "memory")
#define CP_WAIT(n)  asm volatile("cp.async.wait_group %0;" :: "n"(n) : "memory")

// ---------------------------------------------------------------------------
// Scratch (static device globals; explicitly aligned for 16B vector/cp.async)
// ---------------------------------------------------------------------------
__device__ __align__(1024) float g_q [(size_t)Bn * Hn  * Ln * Dn];
__device__ __align__(1024) float g_k [(size_t)Bn * KVn * Ln * Dn];
__device__ __align__(1024) float g_v [(size_t)Bn * KVn * Ln * Dn];
__device__ __align__(1024) float g_ao[(size_t)Bn * Ln * Hn * Dn];

__device__ __align__(1024) __nv_bfloat16 g_Ahi[(size_t)Bn * Ln * HIDn];
__device__ __align__(1024) __nv_bfloat16 g_Alo[(size_t)Bn * Ln * HIDn];
__device__ __align__(1024) __nv_bfloat16 g_WqT_hi[(size_t)Hn * Dn * HIDn];
__device__ __align__(1024) __nv_bfloat16 g_WqT_lo[(size_t)Hn * Dn * HIDn];
__device__ __align__(1024) __nv_bfloat16 g_WkT_hi[(size_t)KVn * Dn * HIDn];
__device__ __align__(1024) __nv_bfloat16 g_WkT_lo[(size_t)KVn * Dn * HIDn];
__device__ __align__(1024) __nv_bfloat16 g_WvT_hi[(size_t)KVn * Dn * HIDn];
__device__ __align__(1024) __nv_bfloat16 g_WvT_lo[(size_t)KVn * Dn * HIDn];
__device__ __align__(1024) __nv_bfloat16 g_WoT_hi[(size_t)HIDn * Hn * Dn];
__device__ __align__(1024) __nv_bfloat16 g_WoT_lo[(size_t)HIDn * Hn * Dn];

// ---------------------------------------------------------------------------
// Split fp32 -> bf16 hi + lo
// ---------------------------------------------------------------------------
template <bool FROM_AO>
__global__ __launch_bounds__(256)
void split_kernel(const float* __restrict__ srcp)
{
    const float* src = FROM_AO ? (const float*)g_ao : srcp;
    size_t i = ((size_t)blockIdx.x * 256 + threadIdx.x) * 4;
    float4 v = *(const float4*)&src[i];
    __nv_bfloat16 h0 = __float2bfloat16(v.x), h1 = __float2bfloat16(v.y);
    __nv_bfloat16 h2 = __float2bfloat16(v.z), h3 = __float2bfloat16(v.w);
    __nv_bfloat16 l0 = __float2bfloat16(v.x - __bfloat162float(h0));
    __nv_bfloat16 l1 = __float2bfloat16(v.y - __bfloat162float(h1));
    __nv_bfloat16 l2 = __float2bfloat16(v.z - __bfloat162float(h2));
    __nv_bfloat16 l3 = __float2bfloat16(v.w - __bfloat162float(h3));
    __nv_bfloat162* ph = (__nv_bfloat162*)&g_Ahi[i];
    __nv_bfloat162* pl = (__nv_bfloat162*)&g_Alo[i];
    ph[0] = __nv_bfloat162(h0, h1); ph[1] = __nv_bfloat162(h2, h3);
    pl[0] = __nv_bfloat162(l0, l1); pl[1] = __nv_bfloat162(l2, l3);
}

// ---------------------------------------------------------------------------
// Transpose + split: W[K=2048][N] f32  ->  WT_hi/lo[N][2048] bf16
// ---------------------------------------------------------------------------
template <int WSEL>
__global__ __launch_bounds__(256)
void transpose_split_kernel(const float* __restrict__ src, int N)
{
    __shared__ float t[32][33];
    const int tx = threadIdx.x & 31, ty = threadIdx.x >> 5;
#pragma unroll
    for (int j = 0; j < 4; j++) {
        int k = blockIdx.y * 32 + ty + j * 8;
        t[ty + j * 8][tx] = src[(size_t)k * N + blockIdx.x * 32 + tx];
    }
    __syncthreads();
    __nv_bfloat16 *dh, *dl;
    if (WSEL == 0)      { dh = g_WqT_hi; dl = g_WqT_lo; }
    else if (WSEL == 1) { dh = g_WkT_hi; dl = g_WkT_lo; }
    else if (WSEL == 2) { dh = g_WvT_hi; dl = g_WvT_lo; }
    else                { dh = g_WoT_hi; dl = g_WoT_lo; }
#pragma unroll
    for (int j = 0; j < 4; j++) {
        int n = blockIdx.x * 32 + ty + j * 8;
        int k = blockIdx.y * 32 + tx;
        float x = t[tx][ty + j * 8];
        __nv_bfloat16 hi = __float2bfloat16(x);
        __nv_bfloat16 lo = __float2bfloat16(x - __bfloat162float(hi));
        dh[(size_t)n * HIDn + k] = hi;
        dl[(size_t)n * HIDn + k] = lo;
    }
}

// ---------------------------------------------------------------------------
// mma.sync split-bf16 GEMM: 128x128 output tile per CTA.
// MODE 0: -> g_q (+RMSNorm+RoPE), 1: -> g_k (+norm+rope), 2: -> g_v,
// MODE 3: A = split(g_ao) -> outp row-major.
//
// SMEM: double-buffered chunks of K=32: 4 tiles (Ahi, Alo, Bhi, Blo),
// each 128 rows x 32 bf16 padded to 40 halves (80B) -> 10240B per tile.
// C epilogue reuses the buffers; stride 132 floats (132 % 4 == 0 so float4
// accesses stay 16B-aligned — stride 130 caused the round-4 trap).
// ---------------------------------------------------------------------------
#define KC      32
#define NKCH    (HIDn / KC)   // 64
#define ROW_B   80            // padded row bytes (40 halves)
#define TILE_B  (128 * ROW_B) // 10240
#define BUF_B   (4 * TILE_B)  // 40960
#define MM_SMEM (2 * BUF_B)   // 81920
#define CSTR    132           // C tile stride in floats (128*132*4 = 67584 B)

template <int MODE>
__global__ __launch_bounds__(256, 2)
void mm_kernel(const float* __restrict__ cosb, const float* __restrict__ sinb,
               const float* __restrict__ nw, float* __restrict__ outp)
{
    extern __shared__ char smc[];
    const uint32_t sb = smem_to_u32(smc);
    float* Cs = (float*)smc;

    const int tid = threadIdx.x;
    const int lane = tid & 31;
    const int wid = tid >> 5;
    const int warp_m = wid >> 2;   // 0..1
    const int warp_n = wid & 3;    // 0..3
    const int m0 = blockIdx.y * 128;
    const int n0 = blockIdx.x * 128;

    const __nv_bfloat16 *Bhi, *Blo;
    if (MODE == 0)      { Bhi = g_WqT_hi; Blo = g_WqT_lo; }
    else if (MODE == 1) { Bhi = g_WkT_hi; Blo = g_WkT_lo; }
    else if (MODE == 2) { Bhi = g_WvT_hi; Blo = g_WvT_lo; }
    else                { Bhi = g_WoT_hi; Blo = g_WoT_lo; }

    float acc[4][4][4];
#pragma unroll
    for (int i = 0; i < 4; i++)
#pragma unroll
        for (int j = 0; j < 4; j++)
#pragma unroll
            for (int r = 0; r < 4; r++) acc[i][j][r] = 0.0f;

    // cp.async loader for one K-chunk into buffer `buf`
    auto load_chunk = [&](int ck, int buf) {
        const int kh = ck * KC;
#pragma unroll
        for (int it = 0; it < 8; it++) {
            const int t   = it >> 1;               // tile 0..3
            const int c   = ((it & 1) << 8) + tid; // 0..511
            const int row = c >> 2;
            const int seg = c & 3;
            const uint32_t sa = sb + buf * BUF_B + t * TILE_B + row * ROW_B + seg * 16;
            const __nv_bfloat16* g;
            if (t == 0)      g = g_Ahi + (size_t)(m0 + row) * HIDn;
            else if (t == 1) g = g_Alo + (size_t)(m0 + row) * HIDn;
            else if (t == 2) g = Bhi   + (size_t)(n0 + row) * HIDn;
            else             g = Blo   + (size_t)(n0 + row) * HIDn;
            cpasync16(sa, g + kh + seg * 8);
        }
    };

    // per-warp ldmatrix base offsets (within a tile)
    const uint32_t aRow = (uint32_t)(warp_m * 64 + (lane & 15)) * ROW_B + ((lane >> 4) << 4);
    const uint32_t bRow = (uint32_t)(warp_n * 32 + (lane & 7)) * ROW_B + (((lane >> 3) & 1) << 4);

    load_chunk(0, 0);
    CP_COMMIT();

    for (int ck = 0; ck < NKCH; ck++) {
        const int buf = ck & 1;
        if (ck + 1 < NKCH) {
            load_chunk(ck + 1, buf ^ 1);
            CP_COMMIT();
            CP_WAIT(1);
        } else {
            CP_WAIT(0);
        }
        __syncthreads();

        const uint32_t base = sb + buf * BUF_B;
#pragma unroll
        for (int ks = 0; ks < 2; ks++) {
            const uint32_t ko = ks * 32;
            uint32_t aHi[16], aX[16], bX[8];
#pragma unroll
            for (int mt = 0; mt < 4; mt++)
                ldm_x4(&aHi[4 * mt], base + aRow + mt * (16 * ROW_B) + ko);
#pragma unroll
            for (int nt = 0; nt < 4; nt++)
                ldm_x2(&bX[2 * nt], base + 2 * TILE_B + bRow + nt * (8 * ROW_B) + ko);
#pragma unroll
            for (int mt = 0; mt < 4; mt++)
#pragma unroll
                for (int nt = 0; nt < 4; nt++)
                    mma16816(acc[mt][nt], &aHi[4 * mt], &bX[2 * nt]);   // hi*hi
#pragma unroll
            for (int mt = 0; mt < 4; mt++)
                ldm_x4(&aX[4 * mt], base + TILE_B + aRow + mt * (16 * ROW_B) + ko);
#pragma unroll
            for (int mt = 0; mt < 4; mt++)
#pragma unroll
                for (int nt = 0; nt < 4; nt++)
                    mma16816(acc[mt][nt], &aX[4 * mt], &bX[2 * nt]);    // lo*hi
#pragma unroll
            for (int nt = 0; nt < 4; nt++)
                ldm_x2(&bX[2 * nt], base + 3 * TILE_B + bRow + nt * (8 * ROW_B) + ko);
#pragma unroll
            for (int mt = 0; mt < 4; mt++)
#pragma unroll
                for (int nt = 0; nt < 4; nt++)
                    mma16816(acc[mt][nt], &aHi[4 * mt], &bX[2 * nt]);   // hi*lo
        }
        __syncthreads();
    }

    // ---- epilogue: accum -> SMEM C tile (stride CSTR floats) ----
    {
        const int rb = warp_m * 64 + (lane >> 2);
        const int cb = warp_n * 32 + (lane & 3) * 2;
#pragma unroll
        for (int mt = 0; mt < 4; mt++)
#pragma unroll
            for (int nt = 0; nt < 4; nt++) {
                const int r = rb + mt * 16, c = cb + nt * 8;
                *(float2*)&Cs[r * CSTR + c]       = make_float2(acc[mt][nt][0], acc[mt][nt][1]);
                *(float2*)&Cs[(r + 8) * CSTR + c] = make_float2(acc[mt][nt][2], acc[mt][nt][3]);
            }
    }
    __syncthreads();

    // ---- fused RMSNorm + RoPE in SMEM (MODE 0/1) ----
    if (MODE == 0 || MODE == 1) {
        if (tid < 128) {
            float* row = Cs + tid * CSTR;
            float ss = 0.0f;
#pragma unroll 16
            for (int d = 0; d < 128; d++) ss += row[d] * row[d];
            const float rr = rsqrtf(ss * (1.0f / Dn) + 1e-6f);
            const int m = m0 + tid;
            const int b = m >> 11;
            const int l = m & (Ln - 1);
            const float* cp = cosb + ((size_t)b * Ln + l) * Dn;
            const float* sp = sinb + ((size_t)b * Ln + l) * Dn;
#pragma unroll 8
            for (int d = 0; d < 64; d++) {
                const float a  = row[d]      * rr * nw[d];
                const float b2 = row[d + 64] * rr * nw[d + 64];
                row[d]      = a * cp[d]       - b2 * sp[d];
                row[d + 64] = b2 * cp[d + 64] + a * sp[d + 64];
            }
        }
        __syncthreads();
    }

    // ---- coalesced writeout ----
#pragma unroll
    for (int it = 0; it < 16; it++) {
        const int idx = it * 256 + tid;   // 0..4095
        const int row = idx >> 5;
        const int seg = idx & 31;
        const float4 v = *(float4*)&Cs[row * CSTR + seg * 4];
        const int m = m0 + row;
        const int b = m >> 11;
        const int l = m & (Ln - 1);
        if (MODE == 3) {
            *(float4*)&outp[(size_t)m * HIDn + n0 + seg * 4] = v;
        } else {
            const int NH = (MODE == 0) ? Hn : KVn;
            const int h = n0 >> 7;
            float* dst = (MODE == 0) ? g_q : (MODE == 1 ? g_k : g_v);
            *(float4*)&dst[(((size_t)b * NH + h) * Ln + l) * Dn + seg * 4] = v;
        }
    }
}

// ---------------------------------------------------------------------------
// Flash attention, fp32 SIMT (unchanged; passing since round 1)
// ---------------------------------------------------------------------------
#define QS_STR 68
#define KS_STR 132
#define ATTN_SMEM_FLOATS (128 * QS_STR + 128 * KS_STR + 128 * 128 + 128 * QS_STR)

__global__ __launch_bounds__(256, 1)
void attn_kernel()
{
    extern __shared__ float sm[];
    float* Qs = sm;
    float* Ks = Qs + 128 * QS_STR;
    float* Vs = Ks + 128 * KS_STR;
    float* Ps = Vs + 128 * 128;

    const int qt = blockIdx.x;
    const int h  = blockIdx.y;
    const int b  = blockIdx.z;
    const int g  = h >> 2;

    const int tid = threadIdx.x;
    const int ty = tid >> 4;
    const int tx = tid & 15;

    const float* Qg = g_q + (((size_t)b * Hn + h) * Ln + qt * 64) * Dn;
    const float* Kg = g_k + ((size_t)b * KVn + g) * Ln * Dn;
    const float* Vg = g_v + ((size_t)b * KVn + g) * Ln * Dn;

    const float SCALE = 0.08838834764831845f;

#pragma unroll
    for (int it = 0; it < 8; it++) {
        int f = tid + it * 256;
        int row = f >> 5, d4 = (f & 31) * 4;
        float4 v = *(const float4*)&Qg[row * Dn + d4];
        Qs[(d4 + 0) * QS_STR + row] = v.x;
        Qs[(d4 + 1) * QS_STR + row] = v.y;
        Qs[(d4 + 2) * QS_STR + row] = v.z;
        Qs[(d4 + 3) * QS_STR + row] = v.w;
    }

    float o[4][8];
#pragma unroll
    for (int i = 0; i < 4; i++)
#pragma unroll
        for (int j = 0; j < 8; j++) o[i][j] = 0.0f;
    float mrow[4] = {-INFINITY, -INFINITY, -INFINITY, -INFINITY};
    float lrow[4] = {0.0f, 0.0f, 0.0f, 0.0f};

    for (int kt = 0; kt < Ln / 128; kt++) {
        __syncthreads();
#pragma unroll
        for (int it = 0; it < 16; it++) {
            int f = tid + it * 256;
            int row = f >> 5, d4 = (f & 31) * 4;
            float4 kv = *(const float4*)&Kg[(size_t)(kt * 128 + row) * Dn + d4];
            Ks[(d4 + 0) * KS_STR + row] = kv.x;
            Ks[(d4 + 1) * KS_STR + row] = kv.y;
            Ks[(d4 + 2) * KS_STR + row] = kv.z;
            Ks[(d4 + 3) * KS_STR + row] = kv.w;
            float4 vv = *(const float4*)&Vg[(size_t)(kt * 128 + row) * Dn + d4];
            *(float4*)&Vs[row * 128 + d4] = vv;
        }
        __syncthreads();

        float s[4][8];
#pragma unroll
        for (int i = 0; i < 4; i++)
#pragma unroll
            for (int j = 0; j < 8; j++) s[i][j] = 0.0f;

        for (int d = 0; d < 128; d++) {
            float4 a  = *(float4*)&Qs[d * QS_STR + ty * 4];
            float4 b0 = *(float4*)&Ks[d * KS_STR + tx * 8];
            float4 b1 = *(float4*)&Ks[d * KS_STR + tx * 8 + 4];
            float av[4] = {a.x, a.y, a.z, a.w};
            float bv[8] = {b0.x, b0.y, b0.z, b0.w, b1.x, b1.y, b1.z, b1.w};
#pragma unroll
            for (int i = 0; i < 4; i++)
#pragma unroll
                for (int j = 0; j < 8; j++) s[i][j] += av[i] * bv[j];
        }

#pragma unroll
        for (int i = 0; i < 4; i++) {
#pragma unroll
            for (int j = 0; j < 8; j++) s[i][j] *= SCALE;
            float rm = s[i][0];
#pragma unroll
            for (int j = 1; j < 8; j++) rm = fmaxf(rm, s[i][j]);
#pragma unroll
            for (int off = 8; off; off >>= 1)
                rm = fmaxf(rm, __shfl_xor_sync(0xffffffffu, rm, off));
            float mnew = fmaxf(mrow[i], rm);
            float corr = __expf(mrow[i] - mnew);
            mrow[i] = mnew;
            float rsum = 0.0f;
#pragma unroll
            for (int j = 0; j < 8; j++) {
                s[i][j] = __expf(s[i][j] - mnew);
                rsum += s[i][j];
            }
#pragma unroll
            for (int off = 8; off; off >>= 1)
                rsum += __shfl_xor_sync(0xffffffffu, rsum, off);
            lrow[i] = lrow[i] * corr + rsum;
#pragma unroll
            for (int j = 0; j < 8; j++) o[i][j] *= corr;
        }

#pragma unroll
        for (int i = 0; i < 4; i++)
#pragma unroll
            for (int j = 0; j < 8; j++)
                Ps[(tx * 8 + j) * QS_STR + (ty * 4 + i)] = s[i][j];
        __syncthreads();

        for (int c = 0; c < 128; c++) {
            float4 a  = *(float4*)&Ps[c * QS_STR + ty * 4];
            float4 b0 = *(float4*)&Vs[c * 128 + tx * 8];
            float4 b1 = *(float4*)&Vs[c * 128 + tx * 8 + 4];
            float av[4] = {a.x, a.y, a.z, a.w};
            float bv[8] = {b0.x, b0.y, b0.z, b0.w, b1.x, b1.y, b1.z, b1.w};
#pragma unroll
            for (int i = 0; i < 4; i++)
#pragma unroll
                for (int j = 0; j < 8; j++) o[i][j] += av[i] * bv[j];
        }
    }

#pragma unroll
    for (int i = 0; i < 4; i++) {
        float inv = 1.0f / lrow[i];
        int l = qt * 64 + ty * 4 + i;
        float* op = g_ao + (((size_t)b * Ln + l) * Hn + h) * Dn + tx * 8;
        float4 v0 = {o[i][0] * inv, o[i][1] * inv, o[i][2] * inv, o[i][3] * inv};
        float4 v1 = {o[i][4] * inv, o[i][5] * inv, o[i][6] * inv, o[i][7] * inv};
        *(float4*)op = v0;
        *(float4*)(op + 4) = v1;
    }
}

// ---------------------------------------------------------------------------
extern "C" void kernel_launch(void* const* d_in, const int* in_sizes, int n_in,
                              void* d_out, int out_size)
{
    const float* hs = (const float*)d_in[0];
    const float* cs = (const float*)d_in[1];
    const float* sn = (const float*)d_in[2];
    const float* Wq = (const float*)d_in[3];
    const float* Wk = (const float*)d_in[4];
    const float* Wv = (const float*)d_in[5];
    const float* Wo = (const float*)d_in[6];
    const float* qw = (const float*)d_in[7];
    const float* kw = (const float*)d_in[8];
    float* out = (float*)d_out;

    cudaFuncSetAttribute(mm_kernel<0>, cudaFuncAttributeMaxDynamicSharedMemorySize, MM_SMEM);
    cudaFuncSetAttribute(mm_kernel<1>, cudaFuncAttributeMaxDynamicSharedMemorySize, MM_SMEM);
    cudaFuncSetAttribute(mm_kernel<2>, cudaFuncAttributeMaxDynamicSharedMemorySize, MM_SMEM);
    cudaFuncSetAttribute(mm_kernel<3>, cudaFuncAttributeMaxDynamicSharedMemorySize, MM_SMEM);

    // Split activations + transpose/split weights
    split_kernel<false><<<(Bn * Ln * HIDn) / 1024, 256>>>(hs);
    transpose_split_kernel<0><<<dim3((Hn * Dn) / 32,  HIDn / 32), 256>>>(Wq, Hn * Dn);
    transpose_split_kernel<1><<<dim3((KVn * Dn) / 32, HIDn / 32), 256>>>(Wk, KVn * Dn);
    transpose_split_kernel<2><<<dim3((KVn * Dn) / 32, HIDn / 32), 256>>>(Wv, KVn * Dn);
    transpose_split_kernel<3><<<dim3(HIDn / 32,       HIDn / 32), 256>>>(Wo, HIDn);

    // QKV projections (tensor-core, fused norm+rope epilogue)
    mm_kernel<0><<<dim3((Hn * Dn) / 128,  (Bn * Ln) / 128), 256, MM_SMEM>>>(cs, sn, qw, nullptr);
    mm_kernel<1><<<dim3((KVn * Dn) / 128, (Bn * Ln) / 128), 256, MM_SMEM>>>(cs, sn, kw, nullptr);
    mm_kernel<2><<<dim3((KVn * Dn) / 128, (Bn * Ln) / 128), 256, MM_SMEM>>>(nullptr, nullptr, nullptr, nullptr);

    // Flash attention (fp32 SIMT)
    {
        int smem_bytes = ATTN_SMEM_FLOATS * (int)sizeof(float);
        cudaFuncSetAttribute(attn_kernel, cudaFuncAttributeMaxDynamicSharedMemorySize, smem_bytes);
        attn_kernel<<<dim3(Ln / 64, Hn, Bn), 256, smem_bytes>>>();
    }

    // Output projection
    split_kernel<true><<<(Bn * Ln * HIDn) / 1024, 256>>>(nullptr);
    mm_kernel<3><<<dim3(HIDn / 128, (Bn * Ln) / 128), 256, MM_SMEM>>>(nullptr, nullptr, nullptr, out);
}

// round 6
// speedup vs baseline: 3.2549x; 2.4136x over previous
#include <cuda_runtime.h>
#include <cuda_bf16.h>
#include <math.h>
#include <stdint.h>

// Problem constants
#define Bn   2
#define Ln   2048
#define Hn   16
#define KVn  4
#define Dn   128
#define HIDn 2048

// ---------------------------------------------------------------------------
// Portable tensor-core helpers (sm_80+ PTX only; harness ptxas targets sm_103
// without the 'a' feature set, so no tcgen05)
// ---------------------------------------------------------------------------
__device__ __forceinline__ uint32_t smem_to_u32(const void* p) {
    uint32_t a;
    asm("{ .reg .u64 t; cvta.to.shared.u64 t, %1; cvt.u32.u64 %0, t; }" : "=r"(a) : "l"(p));
    return a;
}
__device__ __forceinline__ void ldm_x4(uint32_t* r, uint32_t a) {
    asm volatile("ldmatrix.sync.aligned.m8n8.x4.shared.b16 {%0,%1,%2,%3}, [%4];"
        : "=r"(r[0]), "=r"(r[1]), "=r"(r[2]), "=r"(r[3]) : "r"(a));
}
__device__ __forceinline__ void ldm_x4t(uint32_t* r, uint32_t a) {
    asm volatile("ldmatrix.sync.aligned.m8n8.x4.trans.shared.b16 {%0,%1,%2,%3}, [%4];"
        : "=r"(r[0]), "=r"(r[1]), "=r"(r[2]), "=r"(r[3]) : "r"(a));
}
__device__ __forceinline__ void ldm_x2(uint32_t* r, uint32_t a) {
    asm volatile("ldmatrix.sync.aligned.m8n8.x2.shared.b16 {%0,%1}, [%2];"
        : "=r"(r[0]), "=r"(r[1]) : "r"(a));
}
__device__ __forceinline__ void mma16816(float* c, const uint32_t* a, const uint32_t* b) {
    asm volatile("mma.sync.aligned.m16n8k16.row.col.f32.bf16.bf16.f32 "
        "{%0,%1,%2,%3}, {%4,%5,%6,%7}, {%8,%9}, {%0,%1,%2,%3};"
        : "+f"(c[0]), "+f"(c[1]), "+f"(c[2]), "+f"(c[3])
        : "r"(a[0]), "r"(a[1]), "r"(a[2]), "r"(a[3]), "r"(b[0]), "r"(b[1]));
}
__device__ __forceinline__ void cpasync16(uint32_t s, const void* g) {
    asm volatile("cp.async.cg.shared.global [%0], [%1], 16;" :: "r"(s), "l"(g));
}
#define CP_COMMIT() asm volatile("cp.async.commit_group;" ::: "memory")
#define CP_WAIT(n)  asm volatile("cp.async.wait_group %0;" :: "n"(n) : "memory")

__device__ __forceinline__ uint32_t pack_bf16(float x, float y) {
    __nv_bfloat162 h = __float22bfloat162_rn(make_float2(x, y));
    return *(uint32_t*)&h;
}
__device__ __forceinline__ void split2(float x, float y, uint32_t& hi, uint32_t& lo) {
    __nv_bfloat162 h = __float22bfloat162_rn(make_float2(x, y));
    float2 hf = __bfloat1622float2(h);
    hi = *(uint32_t*)&h;
    lo = pack_bf16(x - hf.x, y - hf.y);
}

// FFMA-pipe exp (avoids the MUFU throughput wall: 134M exps at rt=8/SMSP would
// cost ~1ms; this is ~9 FMA-class ops, rel err ~2e-6, valid for x <= 0)
__device__ __forceinline__ float fast_exp(float x) {
    const float L2E = 1.4426950408889634f;
    x = fmaxf(x, -80.0f);
    float t  = fmaf(x, L2E, 12582912.0f);       // round-to-int magic (1.5*2^23)
    int   n  = __float_as_int(t) - 0x4B400000;
    float f  = fmaf(x, L2E, -(t - 12582912.0f)); // f in [-0.5, 0.5]
    float p  = 1.3333558e-3f;
    p = fmaf(p, f, 9.6181291e-3f);
    p = fmaf(p, f, 5.5504109e-2f);
    p = fmaf(p, f, 2.4022651e-1f);
    p = fmaf(p, f, 6.9314718e-1f);
    p = fmaf(p, f, 1.0f);
    return __int_as_float(__float_as_int(p) + (n << 23));
}

// ---------------------------------------------------------------------------
// Scratch (static device globals; aligned for 16B vector/cp.async)
// ---------------------------------------------------------------------------
__device__ __align__(1024) float g_ao[(size_t)Bn * Ln * Hn * Dn];

// split Q/K/V in head-major layout (bf16 hi/lo; Q pre-scaled by D^-0.5)
__device__ __align__(1024) __nv_bfloat16 g_qhi[(size_t)Bn * Hn  * Ln * Dn];
__device__ __align__(1024) __nv_bfloat16 g_qlo[(size_t)Bn * Hn  * Ln * Dn];
__device__ __align__(1024) __nv_bfloat16 g_khi[(size_t)Bn * KVn * Ln * Dn];
__device__ __align__(1024) __nv_bfloat16 g_klo[(size_t)Bn * KVn * Ln * Dn];
__device__ __align__(1024) __nv_bfloat16 g_vhi[(size_t)Bn * KVn * Ln * Dn];
__device__ __align__(1024) __nv_bfloat16 g_vlo[(size_t)Bn * KVn * Ln * Dn];

__device__ __align__(1024) __nv_bfloat16 g_Ahi[(size_t)Bn * Ln * HIDn];
__device__ __align__(1024) __nv_bfloat16 g_Alo[(size_t)Bn * Ln * HIDn];
__device__ __align__(1024) __nv_bfloat16 g_WqT_hi[(size_t)Hn * Dn * HIDn];
__device__ __align__(1024) __nv_bfloat16 g_WqT_lo[(size_t)Hn * Dn * HIDn];
__device__ __align__(1024) __nv_bfloat16 g_WkT_hi[(size_t)KVn * Dn * HIDn];
__device__ __align__(1024) __nv_bfloat16 g_WkT_lo[(size_t)KVn * Dn * HIDn];
__device__ __align__(1024) __nv_bfloat16 g_WvT_hi[(size_t)KVn * Dn * HIDn];
__device__ __align__(1024) __nv_bfloat16 g_WvT_lo[(size_t)KVn * Dn * HIDn];
__device__ __align__(1024) __nv_bfloat16 g_WoT_hi[(size_t)HIDn * Hn * Dn];
__device__ __align__(1024) __nv_bfloat16 g_WoT_lo[(size_t)HIDn * Hn * Dn];

// ---------------------------------------------------------------------------
// Split fp32 -> bf16 hi + lo (activations)
// ---------------------------------------------------------------------------
template <bool FROM_AO>
__global__ __launch_bounds__(256)
void split_kernel(const float* __restrict__ srcp)
{
    const float* src = FROM_AO ? (const float*)g_ao : srcp;
    size_t i = ((size_t)blockIdx.x * 256 + threadIdx.x) * 4;
    float4 v = *(const float4*)&src[i];
    __nv_bfloat16 h0 = __float2bfloat16(v.x), h1 = __float2bfloat16(v.y);
    __nv_bfloat16 h2 = __float2bfloat16(v.z), h3 = __float2bfloat16(v.w);
    __nv_bfloat16 l0 = __float2bfloat16(v.x - __bfloat162float(h0));
    __nv_bfloat16 l1 = __float2bfloat16(v.y - __bfloat162float(h1));
    __nv_bfloat16 l2 = __float2bfloat16(v.z - __bfloat162float(h2));
    __nv_bfloat16 l3 = __float2bfloat16(v.w - __bfloat162float(h3));
    __nv_bfloat162* ph = (__nv_bfloat162*)&g_Ahi[i];
    __nv_bfloat162* pl = (__nv_bfloat162*)&g_Alo[i];
    ph[0] = __nv_bfloat162(h0, h1); ph[1] = __nv_bfloat162(h2, h3);
    pl[0] = __nv_bfloat162(l0, l1); pl[1] = __nv_bfloat162(l2, l3);
}

// ---------------------------------------------------------------------------
// Transpose + split: W[K=2048][N] f32  ->  WT_hi/lo[N][2048] bf16
// ---------------------------------------------------------------------------
template <int WSEL>
__global__ __launch_bounds__(256)
void transpose_split_kernel(const float* __restrict__ src, int N)
{
    __shared__ float t[32][33];
    const int tx = threadIdx.x & 31, ty = threadIdx.x >> 5;
#pragma unroll
    for (int j = 0; j < 4; j++) {
        int k = blockIdx.y * 32 + ty + j * 8;
        t[ty + j * 8][tx] = src[(size_t)k * N + blockIdx.x * 32 + tx];
    }
    __syncthreads();
    __nv_bfloat16 *dh, *dl;
    if (WSEL == 0)      { dh = g_WqT_hi; dl = g_WqT_lo; }
    else if (WSEL == 1) { dh = g_WkT_hi; dl = g_WkT_lo; }
    else if (WSEL == 2) { dh = g_WvT_hi; dl = g_WvT_lo; }
    else                { dh = g_WoT_hi; dl = g_WoT_lo; }
#pragma unroll
    for (int j = 0; j < 4; j++) {
        int n = blockIdx.x * 32 + ty + j * 8;
        int k = blockIdx.y * 32 + tx;
        float x = t[tx][ty + j * 8];
        __nv_bfloat16 hi = __float2bfloat16(x);
        __nv_bfloat16 lo = __float2bfloat16(x - __bfloat162float(hi));
        dh[(size_t)n * HIDn + k] = hi;
        dl[(size_t)n * HIDn + k] = lo;
    }
}

// ---------------------------------------------------------------------------
// mma.sync split-bf16 GEMM: 128x128 output tile per CTA.
// MODE 0: -> g_q hi/lo (+RMSNorm+RoPE+scale), 1: -> g_k hi/lo (+norm+rope),
// MODE 2: -> g_v hi/lo, 3: A = split(g_ao) -> outp fp32 row-major.
// ---------------------------------------------------------------------------
#define KC      32
#define NKCH    (HIDn / KC)   // 64
#define ROW_B   80            // padded row bytes (40 halves)
#define TILE_B  (128 * ROW_B) // 10240
#define BUF_B   (4 * TILE_B)  // 40960
#define MM_SMEM (2 * BUF_B)   // 81920
#define CSTR    132           // C tile stride in floats (stride%4==0 for float4)

template <int MODE>
__global__ __launch_bounds__(256, 2)
void mm_kernel(const float* __restrict__ cosb, const float* __restrict__ sinb,
               const float* __restrict__ nw, float* __restrict__ outp)
{
    extern __shared__ char smc[];
    const uint32_t sb = smem_to_u32(smc);
    float* Cs = (float*)smc;

    const int tid = threadIdx.x;
    const int lane = tid & 31;
    const int wid = tid >> 5;
    const int warp_m = wid >> 2;
    const int warp_n = wid & 3;
    const int m0 = blockIdx.y * 128;
    const int n0 = blockIdx.x * 128;

    const __nv_bfloat16 *Bhi, *Blo;
    if (MODE == 0)      { Bhi = g_WqT_hi; Blo = g_WqT_lo; }
    else if (MODE == 1) { Bhi = g_WkT_hi; Blo = g_WkT_lo; }
    else if (MODE == 2) { Bhi = g_WvT_hi; Blo = g_WvT_lo; }
    else                { Bhi = g_WoT_hi; Blo = g_WoT_lo; }

    float acc[4][4][4];
#pragma unroll
    for (int i = 0; i < 4; i++)
#pragma unroll
        for (int j = 0; j < 4; j++)
#pragma unroll
            for (int r = 0; r < 4; r++) acc[i][j][r] = 0.0f;

    auto load_chunk = [&](int ck, int buf) {
        const int kh = ck * KC;
#pragma unroll
        for (int it = 0; it < 8; it++) {
            const int t   = it >> 1;
            const int c   = ((it & 1) << 8) + tid;
            const int row = c >> 2;
            const int seg = c & 3;
            const uint32_t sa = sb + buf * BUF_B + t * TILE_B + row * ROW_B + seg * 16;
            const __nv_bfloat16* g;
            if (t == 0)      g = g_Ahi + (size_t)(m0 + row) * HIDn;
            else if (t == 1) g = g_Alo + (size_t)(m0 + row) * HIDn;
            else if (t == 2) g = Bhi   + (size_t)(n0 + row) * HIDn;
            else             g = Blo   + (size_t)(n0 + row) * HIDn;
            cpasync16(sa, g + kh + seg * 8);
        }
    };

    const uint32_t aRow = (uint32_t)(warp_m * 64 + (lane & 15)) * ROW_B + ((lane >> 4) << 4);
    const uint32_t bRow = (uint32_t)(warp_n * 32 + (lane & 7)) * ROW_B + (((lane >> 3) & 1) << 4);

    load_chunk(0, 0);
    CP_COMMIT();

    for (int ck = 0; ck < NKCH; ck++) {
        const int buf = ck & 1;
        if (ck + 1 < NKCH) {
            load_chunk(ck + 1, buf ^ 1);
            CP_COMMIT();
            CP_WAIT(1);
        } else {
            CP_WAIT(0);
        }
        __syncthreads();

        const uint32_t base = sb + buf * BUF_B;
#pragma unroll
        for (int ks = 0; ks < 2; ks++) {
            const uint32_t ko = ks * 32;
            uint32_t aHi[16], aX[16], bX[8];
#pragma unroll
            for (int mt = 0; mt < 4; mt++)
                ldm_x4(&aHi[4 * mt], base + aRow + mt * (16 * ROW_B) + ko);
#pragma unroll
            for (int nt = 0; nt < 4; nt++)
                ldm_x2(&bX[2 * nt], base + 2 * TILE_B + bRow + nt * (8 * ROW_B) + ko);
#pragma unroll
            for (int mt = 0; mt < 4; mt++)
#pragma unroll
                for (int nt = 0; nt < 4; nt++)
                    mma16816(acc[mt][nt], &aHi[4 * mt], &bX[2 * nt]);
#pragma unroll
            for (int mt = 0; mt < 4; mt++)
                ldm_x4(&aX[4 * mt], base + TILE_B + aRow + mt * (16 * ROW_B) + ko);
#pragma unroll
            for (int mt = 0; mt < 4; mt++)
#pragma unroll
                for (int nt = 0; nt < 4; nt++)
                    mma16816(acc[mt][nt], &aX[4 * mt], &bX[2 * nt]);
#pragma unroll
            for (int nt = 0; nt < 4; nt++)
                ldm_x2(&bX[2 * nt], base + 3 * TILE_B + bRow + nt * (8 * ROW_B) + ko);
#pragma unroll
            for (int mt = 0; mt < 4; mt++)
#pragma unroll
                for (int nt = 0; nt < 4; nt++)
                    mma16816(acc[mt][nt], &aHi[4 * mt], &bX[2 * nt]);
        }
        __syncthreads();
    }

    // ---- epilogue: accum -> SMEM C tile ----
    {
        const int rb = warp_m * 64 + (lane >> 2);
        const int cb = warp_n * 32 + (lane & 3) * 2;
#pragma unroll
        for (int mt = 0; mt < 4; mt++)
#pragma unroll
            for (int nt = 0; nt < 4; nt++) {
                const int r = rb + mt * 16, c = cb + nt * 8;
                *(float2*)&Cs[r * CSTR + c]       = make_float2(acc[mt][nt][0], acc[mt][nt][1]);
                *(float2*)&Cs[(r + 8) * CSTR + c] = make_float2(acc[mt][nt][2], acc[mt][nt][3]);
            }
    }
    __syncthreads();

    // ---- fused RMSNorm + RoPE (+ Q scale) in SMEM ----
    if (MODE == 0 || MODE == 1) {
        if (tid < 128) {
            float* row = Cs + tid * CSTR;
            float ss = 0.0f;
#pragma unroll 16
            for (int d = 0; d < 128; d++) ss += row[d] * row[d];
            const float rr = rsqrtf(ss * (1.0f / Dn) + 1e-6f);
            const int m = m0 + tid;
            const int b = m >> 11;
            const int l = m & (Ln - 1);
            const float* cp = cosb + ((size_t)b * Ln + l) * Dn;
            const float* sp = sinb + ((size_t)b * Ln + l) * Dn;
            const float post = (MODE == 0) ? 0.08838834764831845f : 1.0f;
#pragma unroll 8
            for (int d = 0; d < 64; d++) {
                const float a  = row[d]      * rr * nw[d];
                const float b2 = row[d + 64] * rr * nw[d + 64];
                row[d]      = (a * cp[d]       - b2 * sp[d])      * post;
                row[d + 64] = (b2 * cp[d + 64] + a * sp[d + 64])  * post;
            }
        }
        __syncthreads();
    }

    // ---- writeout ----
#pragma unroll
    for (int it = 0; it < 16; it++) {
        const int idx = it * 256 + tid;
        const int row = idx >> 5;
        const int seg = idx & 31;
        const float4 v = *(float4*)&Cs[row * CSTR + seg * 4];
        const int m = m0 + row;
        const int b = m >> 11;
        const int l = m & (Ln - 1);
        if (MODE == 3) {
            *(float4*)&outp[(size_t)m * HIDn + n0 + seg * 4] = v;
        } else {
            const int NH = (MODE == 0) ? Hn : KVn;
            const int h = n0 >> 7;
            __nv_bfloat16 *dh, *dl;
            if (MODE == 0)      { dh = g_qhi; dl = g_qlo; }
            else if (MODE == 1) { dh = g_khi; dl = g_klo; }
            else                { dh = g_vhi; dl = g_vlo; }
            const size_t off = (((size_t)b * NH + h) * Ln + l) * Dn + seg * 4;
            uint32_t h01, l01, h23, l23;
            split2(v.x, v.y, h01, l01);
            split2(v.z, v.w, h23, l23);
            uint2 hv = {h01, h23}, lv = {l01, l23};
            *(uint2*)&dh[off] = hv;
            *(uint2*)&dl[off] = lv;
        }
    }
}

// ---------------------------------------------------------------------------
// Tensor-core flash attention (split-bf16, FFMA-pipe softmax exp).
// CTA: 128 queries x 1 head; 8 warps, each warp 16 query rows x full key tile.
// K tile = 64 keys, double-buffered cp.async.
// SMEM halves stride 136 (272B): conflict-free LDSM (272 % 128 = 16).
// ---------------------------------------------------------------------------
#define ASTR_B   272
#define QSUB_B   (128 * ASTR_B)   // 34816 per Q subtile (hi or lo)
#define KSUB_B   (64 * ASTR_B)    // 17408 per KV subtile
#define KV_OFF   (2 * QSUB_B)     // 69632
#define KVBUF_B  (4 * KSUB_B)     // 69632
#define ATTN_SMEM (KV_OFF + 2 * KVBUF_B)  // 208896

__global__ __launch_bounds__(256, 1)
void attn_kernel()
{
    extern __shared__ char sm[];
    const uint32_t sb = smem_to_u32(sm);
    const int tid = threadIdx.x, lane = tid & 31, wid = tid >> 5;
    const int qt = blockIdx.x, h = blockIdx.y, b = blockIdx.z, g = h >> 2;

    const __nv_bfloat16* Qh = g_qhi + (((size_t)b * Hn + h) * Ln + qt * 128) * Dn;
    const __nv_bfloat16* Ql = g_qlo + (((size_t)b * Hn + h) * Ln + qt * 128) * Dn;
    const __nv_bfloat16* Kh = g_khi + ((size_t)b * KVn + g) * Ln * Dn;
    const __nv_bfloat16* Kl = g_klo + ((size_t)b * KVn + g) * Ln * Dn;
    const __nv_bfloat16* Vh = g_vhi + ((size_t)b * KVn + g) * Ln * Dn;
    const __nv_bfloat16* Vl = g_vlo + ((size_t)b * KVn + g) * Ln * Dn;

    // load Q hi/lo (128 x 128 bf16 each)
#pragma unroll
    for (int it = 0; it < 16; it++) {
        const int sub = it >> 3;
        const int r   = (it & 7) * 16 + (tid >> 4);
        const int c   = tid & 15;
        const __nv_bfloat16* src = (sub == 0) ? Qh : Ql;
        cpasync16(sb + sub * QSUB_B + r * ASTR_B + c * 16, src + (size_t)r * Dn + c * 8);
    }

    auto load_kv = [&](int kt, int buf) {
#pragma unroll
        for (int it = 0; it < 16; it++) {
            const int sub = it >> 2;
            const int r   = (it & 3) * 16 + (tid >> 4);
            const int c   = tid & 15;
            const __nv_bfloat16* src;
            if (sub == 0)      src = Kh;
            else if (sub == 1) src = Kl;
            else if (sub == 2) src = Vh;
            else               src = Vl;
            cpasync16(sb + KV_OFF + buf * KVBUF_B + sub * KSUB_B + r * ASTR_B + c * 16,
                      src + (size_t)(kt * 64 + r) * Dn + c * 8);
        }
    };

    load_kv(0, 0);
    CP_COMMIT();

    float o[16][4];
#pragma unroll
    for (int i = 0; i < 16; i++)
#pragma unroll
        for (int j = 0; j < 4; j++) o[i][j] = 0.0f;
    float mrow[2] = {-1e30f, -1e30f};
    float lrow[2] = {0.0f, 0.0f};

    const uint32_t aoffQ = (uint32_t)(wid * 16 + (lane & 15)) * ASTR_B + ((lane >> 4) << 4);
    const uint32_t boffK = (uint32_t)((lane & 7) + ((lane >> 4) << 3)) * ASTR_B
                         + (((lane >> 3) & 1) << 4);
    const uint32_t voffR = (uint32_t)((lane & 7) + (((lane >> 3) & 1) << 3)) * ASTR_B
                         + ((lane >> 4) << 4);

    for (int kt = 0; kt < Ln / 64; kt++) {
        const int buf = kt & 1;
        if (kt + 1 < Ln / 64) {
            load_kv(kt + 1, buf ^ 1);
            CP_COMMIT();
            CP_WAIT(1);
        } else {
            CP_WAIT(0);
        }
        __syncthreads();

        const uint32_t kb = sb + KV_OFF + buf * KVBUF_B;

        // ---- S = Qhi*Khi + Qlo*Khi + Qhi*Klo  (16 x 64 per warp) ----
        float s[8][4];
#pragma unroll
        for (int i = 0; i < 8; i++)
#pragma unroll
            for (int j = 0; j < 4; j++) s[i][j] = 0.0f;

#pragma unroll
        for (int kk = 0; kk < 8; kk++) {
            uint32_t aH[4], aL[4], bb[16];
            ldm_x4(aH, sb + aoffQ + kk * 32);
            ldm_x4(aL, sb + QSUB_B + aoffQ + kk * 32);
#pragma unroll
            for (int p = 0; p < 4; p++)
                ldm_x4(&bb[4 * p], kb + boffK + p * (16 * ASTR_B) + kk * 32);
#pragma unroll
            for (int nt = 0; nt < 8; nt++) mma16816(s[nt], aH, &bb[2 * nt]);
#pragma unroll
            for (int nt = 0; nt < 8; nt++) mma16816(s[nt], aL, &bb[2 * nt]);
#pragma unroll
            for (int p = 0; p < 4; p++)
                ldm_x4(&bb[4 * p], kb + KSUB_B + boffK + p * (16 * ASTR_B) + kk * 32);
#pragma unroll
            for (int nt = 0; nt < 8; nt++) mma16816(s[nt], aH, &bb[2 * nt]);
        }

        // ---- online softmax (rows lane>>2 and +8; quad shuffles) ----
        float mx0 = -1e30f, mx1 = -1e30f;
#pragma unroll
        for (int nt = 0; nt < 8; nt++) {
            mx0 = fmaxf(mx0, fmaxf(s[nt][0], s[nt][1]));
            mx1 = fmaxf(mx1, fmaxf(s[nt][2], s[nt][3]));
        }
        mx0 = fmaxf(mx0, __shfl_xor_sync(0xffffffffu, mx0, 1));
        mx0 = fmaxf(mx0, __shfl_xor_sync(0xffffffffu, mx0, 2));
        mx1 = fmaxf(mx1, __shfl_xor_sync(0xffffffffu, mx1, 1));
        mx1 = fmaxf(mx1, __shfl_xor_sync(0xffffffffu, mx1, 2));
        const float mn0 = fmaxf(mrow[0], mx0);
        const float mn1 = fmaxf(mrow[1], mx1);
        const float cr0 = fast_exp(mrow[0] - mn0);
        const float cr1 = fast_exp(mrow[1] - mn1);
        mrow[0] = mn0; mrow[1] = mn1;

        float sm0 = 0.0f, sm1 = 0.0f;
#pragma unroll
        for (int nt = 0; nt < 8; nt++) {
            s[nt][0] = fast_exp(s[nt][0] - mn0);
            s[nt][1] = fast_exp(s[nt][1] - mn0);
            s[nt][2] = fast_exp(s[nt][2] - mn1);
            s[nt][3] = fast_exp(s[nt][3] - mn1);
            sm0 += s[nt][0] + s[nt][1];
            sm1 += s[nt][2] + s[nt][3];
        }
        sm0 += __shfl_xor_sync(0xffffffffu, sm0, 1);
        sm0 += __shfl_xor_sync(0xffffffffu, sm0, 2);
        sm1 += __shfl_xor_sync(0xffffffffu, sm1, 1);
        sm1 += __shfl_xor_sync(0xffffffffu, sm1, 2);
        lrow[0] = lrow[0] * cr0 + sm0;
        lrow[1] = lrow[1] * cr1 + sm1;
#pragma unroll
        for (int nt = 0; nt < 16; nt++) {
            o[nt][0] *= cr0; o[nt][1] *= cr0;
            o[nt][2] *= cr1; o[nt][3] *= cr1;
        }

        // ---- O += Phi*Vhi + Plo*Vhi + Phi*Vlo ----
#pragma unroll
        for (int kk = 0; kk < 4; kk++) {
            uint32_t pH[4], pL[4];
            split2(s[2 * kk][0],     s[2 * kk][1],     pH[0], pL[0]);
            split2(s[2 * kk][2],     s[2 * kk][3],     pH[1], pL[1]);
            split2(s[2 * kk + 1][0], s[2 * kk + 1][1], pH[2], pL[2]);
            split2(s[2 * kk + 1][2], s[2 * kk + 1][3], pH[3], pL[3]);

            uint32_t vv[32];
            const uint32_t vrow = kk * (16 * ASTR_B) + voffR;
#pragma unroll
            for (int p = 0; p < 8; p++)
                ldm_x4t(&vv[4 * p], kb + 2 * KSUB_B + vrow + p * 32);
#pragma unroll
            for (int nt = 0; nt < 16; nt++) mma16816(o[nt], pH, &vv[2 * nt]);
#pragma unroll
            for (int nt = 0; nt < 16; nt++) mma16816(o[nt], pL, &vv[2 * nt]);
#pragma unroll
            for (int p = 0; p < 8; p++)
                ldm_x4t(&vv[4 * p], kb + 3 * KSUB_B + vrow + p * 32);
#pragma unroll
            for (int nt = 0; nt < 16; nt++) mma16816(o[nt], pH, &vv[2 * nt]);
        }
        __syncthreads();
    }

    // ---- epilogue: normalize, write fp32 to g_ao[b][l][h][d] ----
    const float inv0 = 1.0f / lrow[0];
    const float inv1 = 1.0f / lrow[1];
    const int q0 = qt * 128 + wid * 16 + (lane >> 2);
#pragma unroll
    for (int nt = 0; nt < 16; nt++) {
        const int d = nt * 8 + (lane & 3) * 2;
        float2 v0 = {o[nt][0] * inv0, o[nt][1] * inv0};
        float2 v1 = {o[nt][2] * inv1, o[nt][3] * inv1};
        *(float2*)&g_ao[(((size_t)b * Ln + q0)     * Hn + h) * Dn + d] = v0;
        *(float2*)&g_ao[(((size_t)b * Ln + q0 + 8) * Hn + h) * Dn + d] = v1;
    }
}

// ---------------------------------------------------------------------------
extern "C" void kernel_launch(void* const* d_in, const int* in_sizes, int n_in,
                              void* d_out, int out_size)
{
    const float* hs = (const float*)d_in[0];
    const float* cs = (const float*)d_in[1];
    const float* sn = (const float*)d_in[2];
    const float* Wq = (const float*)d_in[3];
    const float* Wk = (const float*)d_in[4];
    const float* Wv = (const float*)d_in[5];
    const float* Wo = (const float*)d_in[6];
    const float* qw = (const float*)d_in[7];
    const float* kw = (const float*)d_in[8];
    float* out = (float*)d_out;

    cudaFuncSetAttribute(mm_kernel<0>, cudaFuncAttributeMaxDynamicSharedMemorySize, MM_SMEM);
    cudaFuncSetAttribute(mm_kernel<1>, cudaFuncAttributeMaxDynamicSharedMemorySize, MM_SMEM);
    cudaFuncSetAttribute(mm_kernel<2>, cudaFuncAttributeMaxDynamicSharedMemorySize, MM_SMEM);
    cudaFuncSetAttribute(mm_kernel<3>, cudaFuncAttributeMaxDynamicSharedMemorySize, MM_SMEM);
    cudaFuncSetAttribute(attn_kernel, cudaFuncAttributeMaxDynamicSharedMemorySize, ATTN_SMEM);

    // Split activations + transpose/split weights
    split_kernel<false><<<(Bn * Ln * HIDn) / 1024, 256>>>(hs);
    transpose_split_kernel<0><<<dim3((Hn * Dn) / 32,  HIDn / 32), 256>>>(Wq, Hn * Dn);
    transpose_split_kernel<1><<<dim3((KVn * Dn) / 32, HIDn / 32), 256>>>(Wk, KVn * Dn);
    transpose_split_kernel<2><<<dim3((KVn * Dn) / 32, HIDn / 32), 256>>>(Wv, KVn * Dn);
    transpose_split_kernel<3><<<dim3(HIDn / 32,       HIDn / 32), 256>>>(Wo, HIDn);

    // QKV projections (tensor-core; fused norm+rope+scale; emit split bf16)
    mm_kernel<0><<<dim3((Hn * Dn) / 128,  (Bn * Ln) / 128), 256, MM_SMEM>>>(cs, sn, qw, nullptr);
    mm_kernel<1><<<dim3((KVn * Dn) / 128, (Bn * Ln) / 128), 256, MM_SMEM>>>(cs, sn, kw, nullptr);
    mm_kernel<2><<<dim3((KVn * Dn) / 128, (Bn * Ln) / 128), 256, MM_SMEM>>>(nullptr, nullptr, nullptr, nullptr);

    // Tensor-core flash attention
    attn_kernel<<<dim3(Ln / 128, Hn, Bn), 256, ATTN_SMEM>>>();

    // Output projection
    split_kernel<true><<<(Bn * Ln * HIDn) / 1024, 256>>>(nullptr);
    mm_kernel<3><<<dim3(HIDn / 128, (Bn * Ln) / 128), 256, MM_SMEM>>>(nullptr, nullptr, nullptr, out);
}

// round 8
// speedup vs baseline: 3.4345x; 1.0552x over previous
#include <cuda_runtime.h>
#include <cuda_bf16.h>
#include <math.h>
#include <stdint.h>

// Problem constants
#define Bn   2
#define Ln   2048
#define Hn   16
#define KVn  4
#define Dn   128
#define HIDn 2048

// ---------------------------------------------------------------------------
// Portable tensor-core helpers (sm_80+ PTX only; harness ptxas targets sm_103
// without the 'a' feature set, so no tcgen05)
// ---------------------------------------------------------------------------
__device__ __forceinline__ uint32_t smem_to_u32(const void* p) {
    uint32_t a;
    asm("{ .reg .u64 t; cvta.to.shared.u64 t, %1; cvt.u32.u64 %0, t; }" : "=r"(a) : "l"(p));
    return a;
}
__device__ __forceinline__ void ldm_x4(uint32_t* r, uint32_t a) {
    asm volatile("ldmatrix.sync.aligned.m8n8.x4.shared.b16 {%0,%1,%2,%3}, [%4];"
        : "=r"(r[0]), "=r"(r[1]), "=r"(r[2]), "=r"(r[3]) : "r"(a));
}
__device__ __forceinline__ void ldm_x4t(uint32_t* r, uint32_t a) {
    asm volatile("ldmatrix.sync.aligned.m8n8.x4.trans.shared.b16 {%0,%1,%2,%3}, [%4];"
        : "=r"(r[0]), "=r"(r[1]), "=r"(r[2]), "=r"(r[3]) : "r"(a));
}
__device__ __forceinline__ void mma16816(float* c, const uint32_t* a, const uint32_t* b) {
    asm volatile("mma.sync.aligned.m16n8k16.row.col.f32.bf16.bf16.f32 "
        "{%0,%1,%2,%3}, {%4,%5,%6,%7}, {%8,%9}, {%0,%1,%2,%3};"
        : "+f"(c[0]), "+f"(c[1]), "+f"(c[2]), "+f"(c[3])
        : "r"(a[0]), "r"(a[1]), "r"(a[2]), "r"(a[3]), "r"(b[0]), "r"(b[1]));
}
__device__ __forceinline__ void cpasync16(uint32_t s, const void* g) {
    asm volatile("cp.async.cg.shared.global [%0], [%1], 16;" :: "r"(s), "l"(g));
}
#define CP_COMMIT() asm volatile("cp.async.commit_group;" ::: "memory")
#define CP_WAIT(n)  asm volatile("cp.async.wait_group %0;" :: "n"(n) : "memory")

__device__ __forceinline__ uint32_t pack_bf16(float x, float y) {
    __nv_bfloat162 h = __float22bfloat162_rn(make_float2(x, y));
    return *(uint32_t*)&h;
}
__device__ __forceinline__ void split2(float x, float y, uint32_t& hi, uint32_t& lo) {
    __nv_bfloat162 h = __float22bfloat162_rn(make_float2(x, y));
    float2 hf = __bfloat1622float2(h);
    hi = *(uint32_t*)&h;
    lo = pack_bf16(x - hf.x, y - hf.y);
}

// FFMA-pipe exp (avoids the MUFU throughput wall; valid for x <= 0)
__device__ __forceinline__ float fast_exp(float x) {
    const float L2E = 1.4426950408889634f;
    x = fmaxf(x, -80.0f);
    float t  = fmaf(x, L2E, 12582912.0f);
    int   n  = __float_as_int(t) - 0x4B400000;
    float f  = fmaf(x, L2E, -(t - 12582912.0f));
    float p  = 1.3333558e-3f;
    p = fmaf(p, f, 9.6181291e-3f);
    p = fmaf(p, f, 5.5504109e-2f);
    p = fmaf(p, f, 2.4022651e-1f);
    p = fmaf(p, f, 6.9314718e-1f);
    p = fmaf(p, f, 1.0f);
    return __int_as_float(__float_as_int(p) + (n << 23));
}

// ---------------------------------------------------------------------------
// Scratch
// ---------------------------------------------------------------------------
// split Q/K/V head-major (bf16 hi/lo; Q pre-scaled by D^-0.5)
__device__ __align__(1024) __nv_bfloat16 g_qhi[(size_t)Bn * Hn  * Ln * Dn];
__device__ __align__(1024) __nv_bfloat16 g_qlo[(size_t)Bn * Hn  * Ln * Dn];
__device__ __align__(1024) __nv_bfloat16 g_khi[(size_t)Bn * KVn * Ln * Dn];
__device__ __align__(1024) __nv_bfloat16 g_klo[(size_t)Bn * KVn * Ln * Dn];
__device__ __align__(1024) __nv_bfloat16 g_vhi[(size_t)Bn * KVn * Ln * Dn];
__device__ __align__(1024) __nv_bfloat16 g_vlo[(size_t)Bn * KVn * Ln * Dn];

// split activations: hidden_states first; later overwritten by attn output
__device__ __align__(1024) __nv_bfloat16 g_Ahi[(size_t)Bn * Ln * HIDn];
__device__ __align__(1024) __nv_bfloat16 g_Alo[(size_t)Bn * Ln * HIDn];
__device__ __align__(1024) __nv_bfloat16 g_WqT_hi[(size_t)Hn * Dn * HIDn];
__device__ __align__(1024) __nv_bfloat16 g_WqT_lo[(size_t)Hn * Dn * HIDn];
__device__ __align__(1024) __nv_bfloat16 g_WkT_hi[(size_t)KVn * Dn * HIDn];
__device__ __align__(1024) __nv_bfloat16 g_WkT_lo[(size_t)KVn * Dn * HIDn];
__device__ __align__(1024) __nv_bfloat16 g_WvT_hi[(size_t)KVn * Dn * HIDn];
__device__ __align__(1024) __nv_bfloat16 g_WvT_lo[(size_t)KVn * Dn * HIDn];
__device__ __align__(1024) __nv_bfloat16 g_WoT_hi[(size_t)HIDn * Hn * Dn];
__device__ __align__(1024) __nv_bfloat16 g_WoT_lo[(size_t)HIDn * Hn * Dn];

// ---------------------------------------------------------------------------
// Split fp32 -> bf16 hi + lo (hidden states)
// ---------------------------------------------------------------------------
__global__ __launch_bounds__(256)
void split_kernel(const float* __restrict__ src)
{
    size_t i = ((size_t)blockIdx.x * 256 + threadIdx.x) * 4;
    float4 v = *(const float4*)&src[i];
    __nv_bfloat16 h0 = __float2bfloat16(v.x), h1 = __float2bfloat16(v.y);
    __nv_bfloat16 h2 = __float2bfloat16(v.z), h3 = __float2bfloat16(v.w);
    __nv_bfloat16 l0 = __float2bfloat16(v.x - __bfloat162float(h0));
    __nv_bfloat16 l1 = __float2bfloat16(v.y - __bfloat162float(h1));
    __nv_bfloat16 l2 = __float2bfloat16(v.z - __bfloat162float(h2));
    __nv_bfloat16 l3 = __float2bfloat16(v.w - __bfloat162float(h3));
    __nv_bfloat162* ph = (__nv_bfloat162*)&g_Ahi[i];
    __nv_bfloat162* pl = (__nv_bfloat162*)&g_Alo[i];
    ph[0] = __nv_bfloat162(h0, h1); ph[1] = __nv_bfloat162(h2, h3);
    pl[0] = __nv_bfloat162(l0, l1); pl[1] = __nv_bfloat162(l2, l3);
}

// ---------------------------------------------------------------------------
// Transpose + split: W[K=2048][N] f32 -> WT_hi/lo[N][2048] bf16
// ---------------------------------------------------------------------------
template <int WSEL>
__global__ __launch_bounds__(256)
void transpose_split_kernel(const float* __restrict__ src, int N)
{
    __shared__ float t[32][33];
    const int tx = threadIdx.x & 31, ty = threadIdx.x >> 5;
#pragma unroll
    for (int j = 0; j < 4; j++) {
        int k = blockIdx.y * 32 + ty + j * 8;
        t[ty + j * 8][tx] = src[(size_t)k * N + blockIdx.x * 32 + tx];
    }
    __syncthreads();
    __nv_bfloat16 *dh, *dl;
    if (WSEL == 0)      { dh = g_WqT_hi; dl = g_WqT_lo; }
    else if (WSEL == 1) { dh = g_WkT_hi; dl = g_WkT_lo; }
    else if (WSEL == 2) { dh = g_WvT_hi; dl = g_WvT_lo; }
    else                { dh = g_WoT_hi; dl = g_WoT_lo; }
#pragma unroll
    for (int j = 0; j < 4; j++) {
        int n = blockIdx.x * 32 + ty + j * 8;
        int k = blockIdx.y * 32 + tx;
        float x = t[tx][ty + j * 8];
        __nv_bfloat16 hi = __float2bfloat16(x);
        __nv_bfloat16 lo = __float2bfloat16(x - __bfloat162float(hi));
        dh[(size_t)n * HIDn + k] = hi;
        dl[(size_t)n * HIDn + k] = lo;
    }
}

// ---------------------------------------------------------------------------
// mma.sync split-bf16 GEMM, 128x128 tile per CTA.
// QKV==true : one launch for Q|K|V (N=3072 concat), fused norm+rope+scale,
//             emits split bf16 head-major.
// QKV==false: Wo GEMM, A = g_Ahi/lo (attn output), fp32 row-major out.
// ---------------------------------------------------------------------------
#define KC      32
#define NKCH    (HIDn / KC)   // 64
#define ROW_B   80
#define TILE_B  (128 * ROW_B)
#define BUF_B   (4 * TILE_B)
#define MM_SMEM (2 * BUF_B)   // 81920
#define CSTR    132

template <bool QKV>
__global__ __launch_bounds__(256, 2)
void mm_kernel(const float* __restrict__ cosb, const float* __restrict__ sinb,
               const float* __restrict__ qw, const float* __restrict__ kw,
               float* __restrict__ outp)
{
    extern __shared__ char smc[];
    const uint32_t sb = smem_to_u32(smc);
    float* Cs = (float*)smc;

    const int tid = threadIdx.x;
    const int lane = tid & 31;
    const int wid = tid >> 5;
    const int warp_m = wid >> 2;
    const int warp_n = wid & 3;
    const int m0 = blockIdx.y * 128;
    const int n0 = blockIdx.x * 128;

    // operand/epilogue selection (uniform per CTA)
    const __nv_bfloat16 *Bhi, *Blo;
    int bcol = n0, sel = 0;   // sel: 0=Q 1=K 2=V (QKV) / unused (Wo)
    if (QKV) {
        if (n0 < Hn * Dn)                { Bhi = g_WqT_hi; Blo = g_WqT_lo; sel = 0; bcol = n0; }
        else if (n0 < (Hn + KVn) * Dn)   { Bhi = g_WkT_hi; Blo = g_WkT_lo; sel = 1; bcol = n0 - Hn * Dn; }
        else                             { Bhi = g_WvT_hi; Blo = g_WvT_lo; sel = 2; bcol = n0 - (Hn + KVn) * Dn; }
    } else {
        Bhi = g_WoT_hi; Blo = g_WoT_lo; bcol = n0;
    }

    float acc[4][4][4];
#pragma unroll
    for (int i = 0; i < 4; i++)
#pragma unroll
        for (int j = 0; j < 4; j++)
#pragma unroll
            for (int r = 0; r < 4; r++) acc[i][j][r] = 0.0f;

    auto load_chunk = [&](int ck, int buf) {
        const int kh = ck * KC;
#pragma unroll
        for (int it = 0; it < 8; it++) {
            const int t   = it >> 1;
            const int c   = ((it & 1) << 8) + tid;
            const int row = c >> 2;
            const int seg = c & 3;
            const uint32_t sa = sb + buf * BUF_B + t * TILE_B + row * ROW_B + seg * 16;
            const __nv_bfloat16* g;
            if (t == 0)      g = g_Ahi + (size_t)(m0 + row) * HIDn;
            else if (t == 1) g = g_Alo + (size_t)(m0 + row) * HIDn;
            else if (t == 2) g = Bhi   + (size_t)(bcol + row) * HIDn;
            else             g = Blo   + (size_t)(bcol + row) * HIDn;
            cpasync16(sa, g + kh + seg * 8);
        }
    };

    const uint32_t aRow  = (uint32_t)(warp_m * 64 + (lane & 15)) * ROW_B + ((lane >> 4) << 4);
    const uint32_t bRow4 = (uint32_t)(warp_n * 32 + (lane & 7) + ((lane >> 4) << 3)) * ROW_B
                         + (((lane >> 3) & 1) << 4);

    load_chunk(0, 0);
    CP_COMMIT();

    for (int ck = 0; ck < NKCH; ck++) {
        const int buf = ck & 1;
        if (ck + 1 < NKCH) {
            load_chunk(ck + 1, buf ^ 1);
            CP_COMMIT();
            CP_WAIT(1);
        } else {
            CP_WAIT(0);
        }
        __syncthreads();

        const uint32_t base = sb + buf * BUF_B;
#pragma unroll
        for (int ks = 0; ks < 2; ks++) {
            const uint32_t ko = ks * 32;
            uint32_t aHi[16], aX[16], bX[8];
#pragma unroll
            for (int mt = 0; mt < 4; mt++)
                ldm_x4(&aHi[4 * mt], base + aRow + mt * (16 * ROW_B) + ko);
#pragma unroll
            for (int np = 0; np < 2; np++)
                ldm_x4(&bX[4 * np], base + 2 * TILE_B + bRow4 + np * (16 * ROW_B) + ko);
#pragma unroll
            for (int mt = 0; mt < 4; mt++)
#pragma unroll
                for (int nt = 0; nt < 4; nt++)
                    mma16816(acc[mt][nt], &aHi[4 * mt], &bX[2 * nt]);
#pragma unroll
            for (int mt = 0; mt < 4; mt++)
                ldm_x4(&aX[4 * mt], base + TILE_B + aRow + mt * (16 * ROW_B) + ko);
#pragma unroll
            for (int mt = 0; mt < 4; mt++)
#pragma unroll
                for (int nt = 0; nt < 4; nt++)
                    mma16816(acc[mt][nt], &aX[4 * mt], &bX[2 * nt]);
#pragma unroll
            for (int np = 0; np < 2; np++)
                ldm_x4(&bX[4 * np], base + 3 * TILE_B + bRow4 + np * (16 * ROW_B) + ko);
#pragma unroll
            for (int mt = 0; mt < 4; mt++)
#pragma unroll
                for (int nt = 0; nt < 4; nt++)
                    mma16816(acc[mt][nt], &aHi[4 * mt], &bX[2 * nt]);
        }
        __syncthreads();
    }

    // ---- epilogue: accum -> SMEM C tile ----
    {
        const int rb = warp_m * 64 + (lane >> 2);
        const int cb = warp_n * 32 + (lane & 3) * 2;
#pragma unroll
        for (int mt = 0; mt < 4; mt++)
#pragma unroll
            for (int nt = 0; nt < 4; nt++) {
                const int r = rb + mt * 16, c = cb + nt * 8;
                *(float2*)&Cs[r * CSTR + c]       = make_float2(acc[mt][nt][0], acc[mt][nt][1]);
                *(float2*)&Cs[(r + 8) * CSTR + c] = make_float2(acc[mt][nt][2], acc[mt][nt][3]);
            }
    }
    __syncthreads();

    if (QKV) {
        // fused RMSNorm + RoPE (+ Q scale) for Q/K tiles
        if (sel != 2 && tid < 128) {
            const float* nw = (sel == 0) ? qw : kw;
            float* row = Cs + tid * CSTR;
            float ss = 0.0f;
#pragma unroll 16
            for (int d = 0; d < 128; d++) ss += row[d] * row[d];
            const float rr = rsqrtf(ss * (1.0f / Dn) + 1e-6f);
            const int m = m0 + tid;
            const int b = m >> 11;
            const int l = m & (Ln - 1);
            const float* cp = cosb + ((size_t)b * Ln + l) * Dn;
            const float* sp = sinb + ((size_t)b * Ln + l) * Dn;
            const float post = (sel == 0) ? 0.08838834764831845f : 1.0f;
#pragma unroll 8
            for (int d = 0; d < 64; d++) {
                const float a  = row[d]      * rr * nw[d];
                const float b2 = row[d + 64] * rr * nw[d + 64];
                row[d]      = (a * cp[d]       - b2 * sp[d])     * post;
                row[d + 64] = (b2 * cp[d + 64] + a * sp[d + 64]) * post;
            }
        }
        __syncthreads();

        __nv_bfloat16 *dh, *dl;
        int NH, hh;
        if (sel == 0)      { dh = g_qhi; dl = g_qlo; NH = Hn;  hh = bcol >> 7; }
        else if (sel == 1) { dh = g_khi; dl = g_klo; NH = KVn; hh = bcol >> 7; }
        else               { dh = g_vhi; dl = g_vlo; NH = KVn; hh = bcol >> 7; }
#pragma unroll
        for (int it = 0; it < 16; it++) {
            const int idx = it * 256 + tid;
            const int row = idx >> 5;
            const int seg = idx & 31;
            const float4 v = *(float4*)&Cs[row * CSTR + seg * 4];
            const int m = m0 + row;
            const int b = m >> 11;
            const int l = m & (Ln - 1);
            const size_t off = (((size_t)b * NH + hh) * Ln + l) * Dn + seg * 4;
            uint32_t h01, l01, h23, l23;
            split2(v.x, v.y, h01, l01);
            split2(v.z, v.w, h23, l23);
            uint2 hv = {h01, h23}, lv = {l01, l23};
            *(uint2*)&dh[off] = hv;
            *(uint2*)&dl[off] = lv;
        }
    } else {
#pragma unroll
        for (int it = 0; it < 16; it++) {
            const int idx = it * 256 + tid;
            const int row = idx >> 5;
            const int seg = idx & 31;
            const float4 v = *(float4*)&Cs[row * CSTR + seg * 4];
            *(float4*)&outp[(size_t)(m0 + row) * HIDn + n0 + seg * 4] = v;
        }
    }
}

// ---------------------------------------------------------------------------
// Tensor-core flash attention (split-bf16, FFMA softmax exp).
// CTA: 128 queries x 1 head; epilogue emits split bf16 directly into
// g_Ahi/g_Alo (the Wo GEMM's A operand) — no fp32 intermediate.
// ---------------------------------------------------------------------------
#define ASTR_B   272
#define QSUB_B   (128 * ASTR_B)
#define KSUB_B   (64 * ASTR_B)
#define KV_OFF   (2 * QSUB_B)
#define KVBUF_B  (4 * KSUB_B)
#define ATTN_SMEM (KV_OFF + 2 * KVBUF_B)  // 208896

__global__ __launch_bounds__(256, 1)
void attn_kernel()
{
    extern __shared__ char sm[];
    const uint32_t sb = smem_to_u32(sm);
    const int tid = threadIdx.x, lane = tid & 31, wid = tid >> 5;
    const int qt = blockIdx.x, h = blockIdx.y, b = blockIdx.z, g = h >> 2;

    const __nv_bfloat16* Qh = g_qhi + (((size_t)b * Hn + h) * Ln + qt * 128) * Dn;
    const __nv_bfloat16* Ql = g_qlo + (((size_t)b * Hn + h) * Ln + qt * 128) * Dn;
    const __nv_bfloat16* Kh = g_khi + ((size_t)b * KVn + g) * Ln * Dn;
    const __nv_bfloat16* Kl = g_klo + ((size_t)b * KVn + g) * Ln * Dn;
    const __nv_bfloat16* Vh = g_vhi + ((size_t)b * KVn + g) * Ln * Dn;
    const __nv_bfloat16* Vl = g_vlo + ((size_t)b * KVn + g) * Ln * Dn;

#pragma unroll
    for (int it = 0; it < 16; it++) {
        const int sub = it >> 3;
        const int r   = (it & 7) * 16 + (tid >> 4);
        const int c   = tid & 15;
        const __nv_bfloat16* src = (sub == 0) ? Qh : Ql;
        cpasync16(sb + sub * QSUB_B + r * ASTR_B + c * 16, src + (size_t)r * Dn + c * 8);
    }

    auto load_kv = [&](int kt, int buf) {
#pragma unroll
        for (int it = 0; it < 16; it++) {
            const int sub = it >> 2;
            const int r   = (it & 3) * 16 + (tid >> 4);
            const int c   = tid & 15;
            const __nv_bfloat16* src;
            if (sub == 0)      src = Kh;
            else if (sub == 1) src = Kl;
            else if (sub == 2) src = Vh;
            else               src = Vl;
            cpasync16(sb + KV_OFF + buf * KVBUF_B + sub * KSUB_B + r * ASTR_B + c * 16,
                      src + (size_t)(kt * 64 + r) * Dn + c * 8);
        }
    };

    load_kv(0, 0);
    CP_COMMIT();

    float o[16][4];
#pragma unroll
    for (int i = 0; i < 16; i++)
#pragma unroll
        for (int j = 0; j < 4; j++) o[i][j] = 0.0f;
    float mrow[2] = {-1e30f, -1e30f};
    float lrow[2] = {0.0f, 0.0f};

    const uint32_t aoffQ = (uint32_t)(wid * 16 + (lane & 15)) * ASTR_B + ((lane >> 4) << 4);
    const uint32_t boffK = (uint32_t)((lane & 7) + ((lane >> 4) << 3)) * ASTR_B
                         + (((lane >> 3) & 1) << 4);
    const uint32_t voffR = (uint32_t)((lane & 7) + (((lane >> 3) & 1) << 3)) * ASTR_B
                         + ((lane >> 4) << 4);

    for (int kt = 0; kt < Ln / 64; kt++) {
        const int buf = kt & 1;
        if (kt + 1 < Ln / 64) {
            load_kv(kt + 1, buf ^ 1);
            CP_COMMIT();
            CP_WAIT(1);
        } else {
            CP_WAIT(0);
        }
        __syncthreads();

        const uint32_t kb = sb + KV_OFF + buf * KVBUF_B;

        float s[8][4];
#pragma unroll
        for (int i = 0; i < 8; i++)
#pragma unroll
            for (int j = 0; j < 4; j++) s[i][j] = 0.0f;

#pragma unroll
        for (int kk = 0; kk < 8; kk++) {
            uint32_t aH[4], aL[4], bb[16];
            ldm_x4(aH, sb + aoffQ + kk * 32);
            ldm_x4(aL, sb + QSUB_B + aoffQ + kk * 32);
#pragma unroll
            for (int p = 0; p < 4; p++)
                ldm_x4(&bb[4 * p], kb + boffK + p * (16 * ASTR_B) + kk * 32);
#pragma unroll
            for (int nt = 0; nt < 8; nt++) mma16816(s[nt], aH, &bb[2 * nt]);
#pragma unroll
            for (int nt = 0; nt < 8; nt++) mma16816(s[nt], aL, &bb[2 * nt]);
#pragma unroll
            for (int p = 0; p < 4; p++)
                ldm_x4(&bb[4 * p], kb + KSUB_B + boffK + p * (16 * ASTR_B) + kk * 32);
#pragma unroll
            for (int nt = 0; nt < 8; nt++) mma16816(s[nt], aH, &bb[2 * nt]);
        }

        float mx0 = -1e30f, mx1 = -1e30f;
#pragma unroll
        for (int nt = 0; nt < 8; nt++) {
            mx0 = fmaxf(mx0, fmaxf(s[nt][0], s[nt][1]));
            mx1 = fmaxf(mx1, fmaxf(s[nt][2], s[nt][3]));
        }
        mx0 = fmaxf(mx0, __shfl_xor_sync(0xffffffffu, mx0, 1));
        mx0 = fmaxf(mx0, __shfl_xor_sync(0xffffffffu, mx0, 2));
        mx1 = fmaxf(mx1, __shfl_xor_sync(0xffffffffu, mx1, 1));
        mx1 = fmaxf(mx1, __shfl_xor_sync(0xffffffffu, mx1, 2));
        const float mn0 = fmaxf(mrow[0], mx0);
        const float mn1 = fmaxf(mrow[1], mx1);
        const float cr0 = fast_exp(mrow[0] - mn0);
        const float cr1 = fast_exp(mrow[1] - mn1);
        mrow[0] = mn0; mrow[1] = mn1;

        float sm0 = 0.0f, sm1 = 0.0f;
#pragma unroll
        for (int nt = 0; nt < 8; nt++) {
            s[nt][0] = fast_exp(s[nt][0] - mn0);
            s[nt][1] = fast_exp(s[nt][1] - mn0);
            s[nt][2] = fast_exp(s[nt][2] - mn1);
            s[nt][3] = fast_exp(s[nt][3] - mn1);
            sm0 += s[nt][0] + s[nt][1];
            sm1 += s[nt][2] + s[nt][3];
        }
        sm0 += __shfl_xor_sync(0xffffffffu, sm0, 1);
        sm0 += __shfl_xor_sync(0xffffffffu, sm0, 2);
        sm1 += __shfl_xor_sync(0xffffffffu, sm1, 1);
        sm1 += __shfl_xor_sync(0xffffffffu, sm1, 2);
        lrow[0] = lrow[0] * cr0 + sm0;
        lrow[1] = lrow[1] * cr1 + sm1;
#pragma unroll
        for (int nt = 0; nt < 16; nt++) {
            o[nt][0] *= cr0; o[nt][1] *= cr0;
            o[nt][2] *= cr1; o[nt][3] *= cr1;
        }

#pragma unroll
        for (int kk = 0; kk < 4; kk++) {
            uint32_t pH[4], pL[4];
            split2(s[2 * kk][0],     s[2 * kk][1],     pH[0], pL[0]);
            split2(s[2 * kk][2],     s[2 * kk][3],     pH[1], pL[1]);
            split2(s[2 * kk + 1][0], s[2 * kk + 1][1], pH[2], pL[2]);
            split2(s[2 * kk + 1][2], s[2 * kk + 1][3], pH[3], pL[3]);

            uint32_t vv[32];
            const uint32_t vrow = kk * (16 * ASTR_B) + voffR;
#pragma unroll
            for (int p = 0; p < 8; p++)
                ldm_x4t(&vv[4 * p], kb + 2 * KSUB_B + vrow + p * 32);
#pragma unroll
            for (int nt = 0; nt < 16; nt++) mma16816(o[nt], pH, &vv[2 * nt]);
#pragma unroll
            for (int nt = 0; nt < 16; nt++) mma16816(o[nt], pL, &vv[2 * nt]);
#pragma unroll
            for (int p = 0; p < 8; p++)
                ldm_x4t(&vv[4 * p], kb + 3 * KSUB_B + vrow + p * 32);
#pragma unroll
            for (int nt = 0; nt < 16; nt++) mma16816(o[nt], pH, &vv[2 * nt]);
        }
        __syncthreads();
    }

    // ---- epilogue: normalize and emit split bf16 into Wo's A operand ----
    const float inv0 = 1.0f / lrow[0];
    const float inv1 = 1.0f / lrow[1];
    const int q0 = qt * 128 + wid * 16 + (lane >> 2);
    const size_t row0 = ((size_t)b * Ln + q0) * HIDn + h * Dn;
    const size_t row1 = row0 + 8 * HIDn;
#pragma unroll
    for (int nt = 0; nt < 16; nt++) {
        const int d = nt * 8 + (lane & 3) * 2;
        uint32_t hi0, lo0, hi1, lo1;
        split2(o[nt][0] * inv0, o[nt][1] * inv0, hi0, lo0);
        split2(o[nt][2] * inv1, o[nt][3] * inv1, hi1, lo1);
        *(uint32_t*)&g_Ahi[row0 + d] = hi0;
        *(uint32_t*)&g_Alo[row0 + d] = lo0;
        *(uint32_t*)&g_Ahi[row1 + d] = hi1;
        *(uint32_t*)&g_Alo[row1 + d] = lo1;
    }
}

// ---------------------------------------------------------------------------
extern "C" void kernel_launch(void* const* d_in, const int* in_sizes, int n_in,
                              void* d_out, int out_size)
{
    const float* hs = (const float*)d_in[0];
    const float* cs = (const float*)d_in[1];
    const float* sn = (const float*)d_in[2];
    const float* Wq = (const float*)d_in[3];
    const float* Wk = (const float*)d_in[4];
    const float* Wv = (const float*)d_in[5];
    const float* Wo = (const float*)d_in[6];
    const float* qw = (const float*)d_in[7];
    const float* kw = (const float*)d_in[8];
    float* out = (float*)d_out;

    cudaFuncSetAttribute(mm_kernel<true>,  cudaFuncAttributeMaxDynamicSharedMemorySize, MM_SMEM);
    cudaFuncSetAttribute(mm_kernel<false>, cudaFuncAttributeMaxDynamicSharedMemorySize, MM_SMEM);
    cudaFuncSetAttribute(attn_kernel, cudaFuncAttributeMaxDynamicSharedMemorySize, ATTN_SMEM);

    // Prep: split activations, transpose+split weights
    split_kernel<<<(Bn * Ln * HIDn) / 1024, 256>>>(hs);
    transpose_split_kernel<0><<<dim3((Hn * Dn) / 32,  HIDn / 32), 256>>>(Wq, Hn * Dn);
    transpose_split_kernel<1><<<dim3((KVn * Dn) / 32, HIDn / 32), 256>>>(Wk, KVn * Dn);
    transpose_split_kernel<2><<<dim3((KVn * Dn) / 32, HIDn / 32), 256>>>(Wv, KVn * Dn);
    transpose_split_kernel<3><<<dim3(HIDn / 32,       HIDn / 32), 256>>>(Wo, HIDn);

    // Fused QKV projection (single launch, N=3072)
    mm_kernel<true><<<dim3((Hn + 2 * KVn) * Dn / 128, (Bn * Ln) / 128), 256, MM_SMEM>>>(
        cs, sn, qw, kw, nullptr);

    // Tensor-core flash attention (emits split bf16 for Wo)
    attn_kernel<<<dim3(Ln / 128, Hn, Bn), 256, ATTN_SMEM>>>();

    // Output projection
    mm_kernel<false><<<dim3(HIDn / 128, (Bn * Ln) / 128), 256, MM_SMEM>>>(
        nullptr, nullptr, nullptr, nullptr, out);
}

// round 9
// speedup vs baseline: 3.5757x; 1.0411x over previous
#include <cuda_runtime.h>
#include <cuda_bf16.h>
#include <math.h>
#include <stdint.h>

// Problem constants
#define Bn   2
#define Ln   2048
#define Hn   16
#define KVn  4
#define Dn   128
#define HIDn 2048

// ---------------------------------------------------------------------------
// Portable tensor-core helpers (sm_80+ PTX only; harness ptxas targets sm_103
// without the 'a' feature set, so no tcgen05)
// ---------------------------------------------------------------------------
__device__ __forceinline__ uint32_t smem_to_u32(const void* p) {
    uint32_t a;
    asm("{ .reg .u64 t; cvta.to.shared.u64 t, %1; cvt.u32.u64 %0, t; }" : "=r"(a) : "l"(p));
    return a;
}
__device__ __forceinline__ void ldm_x4(uint32_t* r, uint32_t a) {
    asm volatile("ldmatrix.sync.aligned.m8n8.x4.shared.b16 {%0,%1,%2,%3}, [%4];"
        : "=r"(r[0]), "=r"(r[1]), "=r"(r[2]), "=r"(r[3]) : "r"(a));
}
__device__ __forceinline__ void ldm_x4t(uint32_t* r, uint32_t a) {
    asm volatile("ldmatrix.sync.aligned.m8n8.x4.trans.shared.b16 {%0,%1,%2,%3}, [%4];"
        : "=r"(r[0]), "=r"(r[1]), "=r"(r[2]), "=r"(r[3]) : "r"(a));
}
__device__ __forceinline__ void mma16816(float* c, const uint32_t* a, const uint32_t* b) {
    asm volatile("mma.sync.aligned.m16n8k16.row.col.f32.bf16.bf16.f32 "
        "{%0,%1,%2,%3}, {%4,%5,%6,%7}, {%8,%9}, {%0,%1,%2,%3};"
        : "+f"(c[0]), "+f"(c[1]), "+f"(c[2]), "+f"(c[3])
        : "r"(a[0]), "r"(a[1]), "r"(a[2]), "r"(a[3]), "r"(b[0]), "r"(b[1]));
}
__device__ __forceinline__ void cpasync16(uint32_t s, const void* g) {
    asm volatile("cp.async.cg.shared.global [%0], [%1], 16;" :: "r"(s), "l"(g));
}
#define CP_COMMIT() asm volatile("cp.async.commit_group;" ::: "memory")
#define CP_WAIT(n)  asm volatile("cp.async.wait_group %0;" :: "n"(n) : "memory")

__device__ __forceinline__ uint32_t pack_bf16(float x, float y) {
    __nv_bfloat162 h = __float22bfloat162_rn(make_float2(x, y));
    return *(uint32_t*)&h;
}
__device__ __forceinline__ void split2(float x, float y, uint32_t& hi, uint32_t& lo) {
    __nv_bfloat162 h = __float22bfloat162_rn(make_float2(x, y));
    float2 hf = __bfloat1622float2(h);
    hi = *(uint32_t*)&h;
    lo = pack_bf16(x - hf.x, y - hf.y);
}

// FFMA-pipe exp (avoids the MUFU throughput wall; valid for x <= 0)
__device__ __forceinline__ float fast_exp(float x) {
    const float L2E = 1.4426950408889634f;
    x = fmaxf(x, -80.0f);
    float t  = fmaf(x, L2E, 12582912.0f);
    int   n  = __float_as_int(t) - 0x4B400000;
    float f  = fmaf(x, L2E, -(t - 12582912.0f));
    float p  = 1.3333558e-3f;
    p = fmaf(p, f, 9.6181291e-3f);
    p = fmaf(p, f, 5.5504109e-2f);
    p = fmaf(p, f, 2.4022651e-1f);
    p = fmaf(p, f, 6.9314718e-1f);
    p = fmaf(p, f, 1.0f);
    return __int_as_float(__float_as_int(p) + (n << 23));
}

// ---------------------------------------------------------------------------
// Scratch
// ---------------------------------------------------------------------------
#define SPLITK 2
#define KT_PER_SPLIT (Ln / 64 / SPLITK)   // 16 tiles of 64 keys

// split Q/K/V head-major (bf16 hi/lo; Q pre-scaled by D^-0.5)
__device__ __align__(1024) __nv_bfloat16 g_qhi[(size_t)Bn * Hn  * Ln * Dn];
__device__ __align__(1024) __nv_bfloat16 g_qlo[(size_t)Bn * Hn  * Ln * Dn];
__device__ __align__(1024) __nv_bfloat16 g_khi[(size_t)Bn * KVn * Ln * Dn];
__device__ __align__(1024) __nv_bfloat16 g_klo[(size_t)Bn * KVn * Ln * Dn];
__device__ __align__(1024) __nv_bfloat16 g_vhi[(size_t)Bn * KVn * Ln * Dn];
__device__ __align__(1024) __nv_bfloat16 g_vlo[(size_t)Bn * KVn * Ln * Dn];

// split-K attention partials
__device__ __align__(1024) float  g_Opart[(size_t)SPLITK * Bn * Ln * Hn * Dn];
__device__ __align__(1024) float2 g_ml[(size_t)SPLITK * Bn * Hn * Ln];

// split activations: hidden_states first; later overwritten by merged attn out
__device__ __align__(1024) __nv_bfloat16 g_Ahi[(size_t)Bn * Ln * HIDn];
__device__ __align__(1024) __nv_bfloat16 g_Alo[(size_t)Bn * Ln * HIDn];
__device__ __align__(1024) __nv_bfloat16 g_WqT_hi[(size_t)Hn * Dn * HIDn];
__device__ __align__(1024) __nv_bfloat16 g_WqT_lo[(size_t)Hn * Dn * HIDn];
__device__ __align__(1024) __nv_bfloat16 g_WkT_hi[(size_t)KVn * Dn * HIDn];
__device__ __align__(1024) __nv_bfloat16 g_WkT_lo[(size_t)KVn * Dn * HIDn];
__device__ __align__(1024) __nv_bfloat16 g_WvT_hi[(size_t)KVn * Dn * HIDn];
__device__ __align__(1024) __nv_bfloat16 g_WvT_lo[(size_t)KVn * Dn * HIDn];
__device__ __align__(1024) __nv_bfloat16 g_WoT_hi[(size_t)HIDn * Hn * Dn];
__device__ __align__(1024) __nv_bfloat16 g_WoT_lo[(size_t)HIDn * Hn * Dn];

// ---------------------------------------------------------------------------
// Split fp32 -> bf16 hi + lo (hidden states)
// ---------------------------------------------------------------------------
__global__ __launch_bounds__(256)
void split_kernel(const float* __restrict__ src)
{
    size_t i = ((size_t)blockIdx.x * 256 + threadIdx.x) * 4;
    float4 v = *(const float4*)&src[i];
    __nv_bfloat16 h0 = __float2bfloat16(v.x), h1 = __float2bfloat16(v.y);
    __nv_bfloat16 h2 = __float2bfloat16(v.z), h3 = __float2bfloat16(v.w);
    __nv_bfloat16 l0 = __float2bfloat16(v.x - __bfloat162float(h0));
    __nv_bfloat16 l1 = __float2bfloat16(v.y - __bfloat162float(h1));
    __nv_bfloat16 l2 = __float2bfloat16(v.z - __bfloat162float(h2));
    __nv_bfloat16 l3 = __float2bfloat16(v.w - __bfloat162float(h3));
    __nv_bfloat162* ph = (__nv_bfloat162*)&g_Ahi[i];
    __nv_bfloat162* pl = (__nv_bfloat162*)&g_Alo[i];
    ph[0] = __nv_bfloat162(h0, h1); ph[1] = __nv_bfloat162(h2, h3);
    pl[0] = __nv_bfloat162(l0, l1); pl[1] = __nv_bfloat162(l2, l3);
}

// ---------------------------------------------------------------------------
// One launch for all 4 weight transposes+splits.
// grid.x: [0,64) Wq cols, [64,80) Wk, [80,96) Wv, [96,160) Wo; grid.y = K/32.
// ---------------------------------------------------------------------------
__global__ __launch_bounds__(256)
void transpose_split_all(const float* __restrict__ Wq, const float* __restrict__ Wk,
                         const float* __restrict__ Wv, const float* __restrict__ Wo)
{
    const float* src;
    __nv_bfloat16 *dh, *dl;
    int N, c0;
    const int cb = blockIdx.x;
    if (cb < 64)       { src = Wq; dh = g_WqT_hi; dl = g_WqT_lo; N = Hn * Dn;  c0 = cb; }
    else if (cb < 80)  { src = Wk; dh = g_WkT_hi; dl = g_WkT_lo; N = KVn * Dn; c0 = cb - 64; }
    else if (cb < 96)  { src = Wv; dh = g_WvT_hi; dl = g_WvT_lo; N = KVn * Dn; c0 = cb - 80; }
    else               { src = Wo; dh = g_WoT_hi; dl = g_WoT_lo; N = HIDn;     c0 = cb - 96; }

    __shared__ float t[32][33];
    const int tx = threadIdx.x & 31, ty = threadIdx.x >> 5;
#pragma unroll
    for (int j = 0; j < 4; j++) {
        int k = blockIdx.y * 32 + ty + j * 8;
        t[ty + j * 8][tx] = src[(size_t)k * N + c0 * 32 + tx];
    }
    __syncthreads();
#pragma unroll
    for (int j = 0; j < 4; j++) {
        int n = c0 * 32 + ty + j * 8;
        int k = blockIdx.y * 32 + tx;
        float x = t[tx][ty + j * 8];
        __nv_bfloat16 hi = __float2bfloat16(x);
        __nv_bfloat16 lo = __float2bfloat16(x - __bfloat162float(hi));
        dh[(size_t)n * HIDn + k] = hi;
        dl[(size_t)n * HIDn + k] = lo;
    }
}

// ---------------------------------------------------------------------------
// mma.sync split-bf16 GEMM, 128x128 tile per CTA (unchanged from round 8).
// ---------------------------------------------------------------------------
#define KC      32
#define NKCH    (HIDn / KC)
#define ROW_B   80
#define TILE_B  (128 * ROW_B)
#define BUF_B   (4 * TILE_B)
#define MM_SMEM (2 * BUF_B)
#define CSTR    132

template <bool QKV>
__global__ __launch_bounds__(256, 2)
void mm_kernel(const float* __restrict__ cosb, const float* __restrict__ sinb,
               const float* __restrict__ qw, const float* __restrict__ kw,
               float* __restrict__ outp)
{
    extern __shared__ char smc[];
    const uint32_t sb = smem_to_u32(smc);
    float* Cs = (float*)smc;

    const int tid = threadIdx.x;
    const int lane = tid & 31;
    const int wid = tid >> 5;
    const int warp_m = wid >> 2;
    const int warp_n = wid & 3;
    const int m0 = blockIdx.y * 128;
    const int n0 = blockIdx.x * 128;

    const __nv_bfloat16 *Bhi, *Blo;
    int bcol = n0, sel = 0;
    if (QKV) {
        if (n0 < Hn * Dn)                { Bhi = g_WqT_hi; Blo = g_WqT_lo; sel = 0; bcol = n0; }
        else if (n0 < (Hn + KVn) * Dn)   { Bhi = g_WkT_hi; Blo = g_WkT_lo; sel = 1; bcol = n0 - Hn * Dn; }
        else                             { Bhi = g_WvT_hi; Blo = g_WvT_lo; sel = 2; bcol = n0 - (Hn + KVn) * Dn; }
    } else {
        Bhi = g_WoT_hi; Blo = g_WoT_lo; bcol = n0;
    }

    float acc[4][4][4];
#pragma unroll
    for (int i = 0; i < 4; i++)
#pragma unroll
        for (int j = 0; j < 4; j++)
#pragma unroll
            for (int r = 0; r < 4; r++) acc[i][j][r] = 0.0f;

    auto load_chunk = [&](int ck, int buf) {
        const int kh = ck * KC;
#pragma unroll
        for (int it = 0; it < 8; it++) {
            const int t   = it >> 1;
            const int c   = ((it & 1) << 8) + tid;
            const int row = c >> 2;
            const int seg = c & 3;
            const uint32_t sa = sb + buf * BUF_B + t * TILE_B + row * ROW_B + seg * 16;
            const __nv_bfloat16* g;
            if (t == 0)      g = g_Ahi + (size_t)(m0 + row) * HIDn;
            else if (t == 1) g = g_Alo + (size_t)(m0 + row) * HIDn;
            else if (t == 2) g = Bhi   + (size_t)(bcol + row) * HIDn;
            else             g = Blo   + (size_t)(bcol + row) * HIDn;
            cpasync16(sa, g + kh + seg * 8);
        }
    };

    const uint32_t aRow  = (uint32_t)(warp_m * 64 + (lane & 15)) * ROW_B + ((lane >> 4) << 4);
    const uint32_t bRow4 = (uint32_t)(warp_n * 32 + (lane & 7) + ((lane >> 4) << 3)) * ROW_B
                         + (((lane >> 3) & 1) << 4);

    load_chunk(0, 0);
    CP_COMMIT();

    for (int ck = 0; ck < NKCH; ck++) {
        const int buf = ck & 1;
        if (ck + 1 < NKCH) {
            load_chunk(ck + 1, buf ^ 1);
            CP_COMMIT();
            CP_WAIT(1);
        } else {
            CP_WAIT(0);
        }
        __syncthreads();

        const uint32_t base = sb + buf * BUF_B;
#pragma unroll
        for (int ks = 0; ks < 2; ks++) {
            const uint32_t ko = ks * 32;
            uint32_t aHi[16], aX[16], bX[8];
#pragma unroll
            for (int mt = 0; mt < 4; mt++)
                ldm_x4(&aHi[4 * mt], base + aRow + mt * (16 * ROW_B) + ko);
#pragma unroll
            for (int np = 0; np < 2; np++)
                ldm_x4(&bX[4 * np], base + 2 * TILE_B + bRow4 + np * (16 * ROW_B) + ko);
#pragma unroll
            for (int mt = 0; mt < 4; mt++)
#pragma unroll
                for (int nt = 0; nt < 4; nt++)
                    mma16816(acc[mt][nt], &aHi[4 * mt], &bX[2 * nt]);
#pragma unroll
            for (int mt = 0; mt < 4; mt++)
                ldm_x4(&aX[4 * mt], base + TILE_B + aRow + mt * (16 * ROW_B) + ko);
#pragma unroll
            for (int mt = 0; mt < 4; mt++)
#pragma unroll
                for (int nt = 0; nt < 4; nt++)
                    mma16816(acc[mt][nt], &aX[4 * mt], &bX[2 * nt]);
#pragma unroll
            for (int np = 0; np < 2; np++)
                ldm_x4(&bX[4 * np], base + 3 * TILE_B + bRow4 + np * (16 * ROW_B) + ko);
#pragma unroll
            for (int mt = 0; mt < 4; mt++)
#pragma unroll
                for (int nt = 0; nt < 4; nt++)
                    mma16816(acc[mt][nt], &aHi[4 * mt], &bX[2 * nt]);
        }
        __syncthreads();
    }

    {
        const int rb = warp_m * 64 + (lane >> 2);
        const int cb = warp_n * 32 + (lane & 3) * 2;
#pragma unroll
        for (int mt = 0; mt < 4; mt++)
#pragma unroll
            for (int nt = 0; nt < 4; nt++) {
                const int r = rb + mt * 16, c = cb + nt * 8;
                *(float2*)&Cs[r * CSTR + c]       = make_float2(acc[mt][nt][0], acc[mt][nt][1]);
                *(float2*)&Cs[(r + 8) * CSTR + c] = make_float2(acc[mt][nt][2], acc[mt][nt][3]);
            }
    }
    __syncthreads();

    if (QKV) {
        if (sel != 2 && tid < 128) {
            const float* nw = (sel == 0) ? qw : kw;
            float* row = Cs + tid * CSTR;
            float ss = 0.0f;
#pragma unroll 16
            for (int d = 0; d < 128; d++) ss += row[d] * row[d];
            const float rr = rsqrtf(ss * (1.0f / Dn) + 1e-6f);
            const int m = m0 + tid;
            const int b = m >> 11;
            const int l = m & (Ln - 1);
            const float* cp = cosb + ((size_t)b * Ln + l) * Dn;
            const float* sp = sinb + ((size_t)b * Ln + l) * Dn;
            const float post = (sel == 0) ? 0.08838834764831845f : 1.0f;
#pragma unroll 8
            for (int d = 0; d < 64; d++) {
                const float a  = row[d]      * rr * nw[d];
                const float b2 = row[d + 64] * rr * nw[d + 64];
                row[d]      = (a * cp[d]       - b2 * sp[d])     * post;
                row[d + 64] = (b2 * cp[d + 64] + a * sp[d + 64]) * post;
            }
        }
        __syncthreads();

        __nv_bfloat16 *dh, *dl;
        int NH, hh;
        if (sel == 0)      { dh = g_qhi; dl = g_qlo; NH = Hn;  hh = bcol >> 7; }
        else if (sel == 1) { dh = g_khi; dl = g_klo; NH = KVn; hh = bcol >> 7; }
        else               { dh = g_vhi; dl = g_vlo; NH = KVn; hh = bcol >> 7; }
#pragma unroll
        for (int it = 0; it < 16; it++) {
            const int idx = it * 256 + tid;
            const int row = idx >> 5;
            const int seg = idx & 31;
            const float4 v = *(float4*)&Cs[row * CSTR + seg * 4];
            const int m = m0 + row;
            const int b = m >> 11;
            const int l = m & (Ln - 1);
            const size_t off = (((size_t)b * NH + hh) * Ln + l) * Dn + seg * 4;
            uint32_t h01, l01, h23, l23;
            split2(v.x, v.y, h01, l01);
            split2(v.z, v.w, h23, l23);
            uint2 hv = {h01, h23}, lv = {l01, l23};
            *(uint2*)&dh[off] = hv;
            *(uint2*)&dl[off] = lv;
        }
    } else {
#pragma unroll
        for (int it = 0; it < 16; it++) {
            const int idx = it * 256 + tid;
            const int row = idx >> 5;
            const int seg = idx & 31;
            const float4 v = *(float4*)&Cs[row * CSTR + seg * 4];
            *(float4*)&outp[(size_t)(m0 + row) * HIDn + n0 + seg * 4] = v;
        }
    }
}

// ---------------------------------------------------------------------------
// Tensor-core flash attention, split-K over 2 CTAs per (qt,h,b).
// blockIdx.z = b*SPLITK + kz; CTA handles key tiles [kz*16, kz*16+16).
// Epilogue writes un-normalized partial O (fp32) + per-row (m,l).
// ---------------------------------------------------------------------------
#define ASTR_B   272
#define QSUB_B   (128 * ASTR_B)
#define KSUB_B   (64 * ASTR_B)
#define KV_OFF   (2 * QSUB_B)
#define KVBUF_B  (4 * KSUB_B)
#define ATTN_SMEM (KV_OFF + 2 * KVBUF_B)  // 208896

__global__ __launch_bounds__(256, 1)
void attn_kernel()
{
    extern __shared__ char sm[];
    const uint32_t sb = smem_to_u32(sm);
    const int tid = threadIdx.x, lane = tid & 31, wid = tid >> 5;
    const int qt = blockIdx.x, h = blockIdx.y;
    const int b  = blockIdx.z >> 1, kz = blockIdx.z & 1;
    const int g  = h >> 2;

    const __nv_bfloat16* Qh = g_qhi + (((size_t)b * Hn + h) * Ln + qt * 128) * Dn;
    const __nv_bfloat16* Ql = g_qlo + (((size_t)b * Hn + h) * Ln + qt * 128) * Dn;
    const __nv_bfloat16* Kh = g_khi + ((size_t)b * KVn + g) * Ln * Dn;
    const __nv_bfloat16* Kl = g_klo + ((size_t)b * KVn + g) * Ln * Dn;
    const __nv_bfloat16* Vh = g_vhi + ((size_t)b * KVn + g) * Ln * Dn;
    const __nv_bfloat16* Vl = g_vlo + ((size_t)b * KVn + g) * Ln * Dn;

#pragma unroll
    for (int it = 0; it < 16; it++) {
        const int sub = it >> 3;
        const int r   = (it & 7) * 16 + (tid >> 4);
        const int c   = tid & 15;
        const __nv_bfloat16* src = (sub == 0) ? Qh : Ql;
        cpasync16(sb + sub * QSUB_B + r * ASTR_B + c * 16, src + (size_t)r * Dn + c * 8);
    }

    auto load_kv = [&](int kt, int buf) {
#pragma unroll
        for (int it = 0; it < 16; it++) {
            const int sub = it >> 2;
            const int r   = (it & 3) * 16 + (tid >> 4);
            const int c   = tid & 15;
            const __nv_bfloat16* src;
            if (sub == 0)      src = Kh;
            else if (sub == 1) src = Kl;
            else if (sub == 2) src = Vh;
            else               src = Vl;
            cpasync16(sb + KV_OFF + buf * KVBUF_B + sub * KSUB_B + r * ASTR_B + c * 16,
                      src + (size_t)(kt * 64 + r) * Dn + c * 8);
        }
    };

    const int KT0 = kz * KT_PER_SPLIT;
    const int KT1 = KT0 + KT_PER_SPLIT;
    load_kv(KT0, 0);
    CP_COMMIT();

    float o[16][4];
#pragma unroll
    for (int i = 0; i < 16; i++)
#pragma unroll
        for (int j = 0; j < 4; j++) o[i][j] = 0.0f;
    float mrow[2] = {-1e30f, -1e30f};
    float lrow[2] = {0.0f, 0.0f};

    const uint32_t aoffQ = (uint32_t)(wid * 16 + (lane & 15)) * ASTR_B + ((lane >> 4) << 4);
    const uint32_t boffK = (uint32_t)((lane & 7) + ((lane >> 4) << 3)) * ASTR_B
                         + (((lane >> 3) & 1) << 4);
    const uint32_t voffR = (uint32_t)((lane & 7) + (((lane >> 3) & 1) << 3)) * ASTR_B
                         + ((lane >> 4) << 4);

    for (int kt = KT0; kt < KT1; kt++) {
        const int buf = kt & 1;
        if (kt + 1 < KT1) {
            load_kv(kt + 1, buf ^ 1);
            CP_COMMIT();
            CP_WAIT(1);
        } else {
            CP_WAIT(0);
        }
        __syncthreads();

        const uint32_t kb = sb + KV_OFF + buf * KVBUF_B;

        float s[8][4];
#pragma unroll
        for (int i = 0; i < 8; i++)
#pragma unroll
            for (int j = 0; j < 4; j++) s[i][j] = 0.0f;

#pragma unroll
        for (int kk = 0; kk < 8; kk++) {
            uint32_t aH[4], aL[4], bb[16];
            ldm_x4(aH, sb + aoffQ + kk * 32);
            ldm_x4(aL, sb + QSUB_B + aoffQ + kk * 32);
#pragma unroll
            for (int p = 0; p < 4; p++)
                ldm_x4(&bb[4 * p], kb + boffK + p * (16 * ASTR_B) + kk * 32);
#pragma unroll
            for (int nt = 0; nt < 8; nt++) mma16816(s[nt], aH, &bb[2 * nt]);
#pragma unroll
            for (int nt = 0; nt < 8; nt++) mma16816(s[nt], aL, &bb[2 * nt]);
#pragma unroll
            for (int p = 0; p < 4; p++)
                ldm_x4(&bb[4 * p], kb + KSUB_B + boffK + p * (16 * ASTR_B) + kk * 32);
#pragma unroll
            for (int nt = 0; nt < 8; nt++) mma16816(s[nt], aH, &bb[2 * nt]);
        }

        float mx0 = -1e30f, mx1 = -1e30f;
#pragma unroll
        for (int nt = 0; nt < 8; nt++) {
            mx0 = fmaxf(mx0, fmaxf(s[nt][0], s[nt][1]));
            mx1 = fmaxf(mx1, fmaxf(s[nt][2], s[nt][3]));
        }
        mx0 = fmaxf(mx0, __shfl_xor_sync(0xffffffffu, mx0, 1));
        mx0 = fmaxf(mx0, __shfl_xor_sync(0xffffffffu, mx0, 2));
        mx1 = fmaxf(mx1, __shfl_xor_sync(0xffffffffu, mx1, 1));
        mx1 = fmaxf(mx1, __shfl_xor_sync(0xffffffffu, mx1, 2));
        const float mn0 = fmaxf(mrow[0], mx0);
        const float mn1 = fmaxf(mrow[1], mx1);
        const float cr0 = fast_exp(mrow[0] - mn0);
        const float cr1 = fast_exp(mrow[1] - mn1);
        mrow[0] = mn0; mrow[1] = mn1;

        float sm0 = 0.0f, sm1 = 0.0f;
#pragma unroll
        for (int nt = 0; nt < 8; nt++) {
            s[nt][0] = fast_exp(s[nt][0] - mn0);
            s[nt][1] = fast_exp(s[nt][1] - mn0);
            s[nt][2] = fast_exp(s[nt][2] - mn1);
            s[nt][3] = fast_exp(s[nt][3] - mn1);
            sm0 += s[nt][0] + s[nt][1];
            sm1 += s[nt][2] + s[nt][3];
        }
        sm0 += __shfl_xor_sync(0xffffffffu, sm0, 1);
        sm0 += __shfl_xor_sync(0xffffffffu, sm0, 2);
        sm1 += __shfl_xor_sync(0xffffffffu, sm1, 1);
        sm1 += __shfl_xor_sync(0xffffffffu, sm1, 2);
        lrow[0] = lrow[0] * cr0 + sm0;
        lrow[1] = lrow[1] * cr1 + sm1;
#pragma unroll
        for (int nt = 0; nt < 16; nt++) {
            o[nt][0] *= cr0; o[nt][1] *= cr0;
            o[nt][2] *= cr1; o[nt][3] *= cr1;
        }

#pragma unroll
        for (int kk = 0; kk < 4; kk++) {
            uint32_t pH[4], pL[4];
            split2(s[2 * kk][0],     s[2 * kk][1],     pH[0], pL[0]);
            split2(s[2 * kk][2],     s[2 * kk][3],     pH[1], pL[1]);
            split2(s[2 * kk + 1][0], s[2 * kk + 1][1], pH[2], pL[2]);
            split2(s[2 * kk + 1][2], s[2 * kk + 1][3], pH[3], pL[3]);

            uint32_t vv[32];
            const uint32_t vrow = kk * (16 * ASTR_B) + voffR;
#pragma unroll
            for (int p = 0; p < 8; p++)
                ldm_x4t(&vv[4 * p], kb + 2 * KSUB_B + vrow + p * 32);
#pragma unroll
            for (int nt = 0; nt < 16; nt++) mma16816(o[nt], pH, &vv[2 * nt]);
#pragma unroll
            for (int nt = 0; nt < 16; nt++) mma16816(o[nt], pL, &vv[2 * nt]);
#pragma unroll
            for (int p = 0; p < 8; p++)
                ldm_x4t(&vv[4 * p], kb + 3 * KSUB_B + vrow + p * 32);
#pragma unroll
            for (int nt = 0; nt < 16; nt++) mma16816(o[nt], pH, &vv[2 * nt]);
        }
        __syncthreads();
    }

    // ---- epilogue: write un-normalized partial O + (m,l) ----
    const int q0 = qt * 128 + wid * 16 + (lane >> 2);
    if ((lane & 3) == 0) {
        g_ml[(((size_t)kz * Bn + b) * Hn + h) * Ln + q0]     = make_float2(mrow[0], lrow[0]);
        g_ml[(((size_t)kz * Bn + b) * Hn + h) * Ln + q0 + 8] = make_float2(mrow[1], lrow[1]);
    }
    const size_t r0 = (((size_t)kz * Bn + b) * Ln + q0) * (Hn * Dn) + h * Dn;
    const size_t r1 = r0 + (size_t)8 * Hn * Dn;
#pragma unroll
    for (int nt = 0; nt < 16; nt++) {
        const int d = nt * 8 + (lane & 3) * 2;
        *(float2*)&g_Opart[r0 + d] = make_float2(o[nt][0], o[nt][1]);
        *(float2*)&g_Opart[r1 + d] = make_float2(o[nt][2], o[nt][3]);
    }
}

// ---------------------------------------------------------------------------
// Merge the SPLITK partials, normalize, emit split bf16 into g_Ahi/g_Alo.
// Destination linear index == partial-O index (HID == Hn*Dn).
// ---------------------------------------------------------------------------
__global__ __launch_bounds__(256)
void merge_kernel()
{
    const size_t gid = (size_t)blockIdx.x * 256 + threadIdx.x;
    const size_t e4 = gid * 4;                 // element index, multiple of 4
    const size_t row = e4 >> 7;                // (b*Ln + l)*Hn + h
    const int hh = (int)(row & (Hn - 1));
    const size_t bl = row >> 4;                // b*Ln + l
    const int l = (int)(bl & (Ln - 1));
    const int b = (int)(bl >> 11);

    const float2 ml0 = g_ml[(((size_t)0 * Bn + b) * Hn + hh) * Ln + l];
    const float2 ml1 = g_ml[(((size_t)1 * Bn + b) * Hn + hh) * Ln + l];
    const float ms = fmaxf(ml0.x, ml1.x);
    const float w0 = fast_exp(ml0.x - ms);
    const float w1 = fast_exp(ml1.x - ms);
    const float inv = 1.0f / (ml0.y * w0 + ml1.y * w1);
    const float f0 = w0 * inv, f1 = w1 * inv;

    const float4 vA = *(const float4*)&g_Opart[e4];
    const float4 vB = *(const float4*)&g_Opart[(size_t)Bn * Ln * Hn * Dn + e4];
    const float x0 = vA.x * f0 + vB.x * f1;
    const float x1 = vA.y * f0 + vB.y * f1;
    const float x2 = vA.z * f0 + vB.z * f1;
    const float x3 = vA.w * f0 + vB.w * f1;

    uint32_t h01, l01, h23, l23;
    split2(x0, x1, h01, l01);
    split2(x2, x3, h23, l23);
    uint2 hv = {h01, h23}, lv = {l01, l23};
    *(uint2*)&g_Ahi[e4] = hv;
    *(uint2*)&g_Alo[e4] = lv;
}

// ---------------------------------------------------------------------------
extern "C" void kernel_launch(void* const* d_in, const int* in_sizes, int n_in,
                              void* d_out, int out_size)
{
    const float* hs = (const float*)d_in[0];
    const float* cs = (const float*)d_in[1];
    const float* sn = (const float*)d_in[2];
    const float* Wq = (const float*)d_in[3];
    const float* Wk = (const float*)d_in[4];
    const float* Wv = (const float*)d_in[5];
    const float* Wo = (const float*)d_in[6];
    const float* qw = (const float*)d_in[7];
    const float* kw = (const float*)d_in[8];
    float* out = (float*)d_out;

    cudaFuncSetAttribute(mm_kernel<true>,  cudaFuncAttributeMaxDynamicSharedMemorySize, MM_SMEM);
    cudaFuncSetAttribute(mm_kernel<false>, cudaFuncAttributeMaxDynamicSharedMemorySize, MM_SMEM);
    cudaFuncSetAttribute(attn_kernel, cudaFuncAttributeMaxDynamicSharedMemorySize, ATTN_SMEM);

    // Prep: split activations, all weight transposes in one launch
    split_kernel<<<(Bn * Ln * HIDn) / 1024, 256>>>(hs);
    transpose_split_all<<<dim3(160, HIDn / 32), 256>>>(Wq, Wk, Wv, Wo);

    // Fused QKV projection (single launch, N=3072)
    mm_kernel<true><<<dim3((Hn + 2 * KVn) * Dn / 128, (Bn * Ln) / 128), 256, MM_SMEM>>>(
        cs, sn, qw, kw, nullptr);

    // Split-K flash attention + merge
    attn_kernel<<<dim3(Ln / 128, Hn, Bn * SPLITK), 256, ATTN_SMEM>>>();
    merge_kernel<<<(Bn * Ln * Hn * Dn) / 1024, 256>>>();

    // Output projection
    mm_kernel<false><<<dim3(HIDn / 128, (Bn * Ln) / 128), 256, MM_SMEM>>>(
        nullptr, nullptr, nullptr, nullptr, out);
}